// round 11
// baseline (speedup 1.0000x reference)
#include <cuda_runtime.h>
#include <cuda_bf16.h>
#include <cstdint>

#define M_ROWS 16384
#define KD 256
#define NC 8192
#define QUANT_ELEMS 4194304
#define ONEHOT_ELEMS 134217728
#define THRD 1.25e-4f   // candidate band in dot space (= 2.5e-4 dist / 2)
#define GEMM_CTAS 128
#define ZERO_CTAS 20
#define TOTAL_CTAS (GEMM_CTAS + ZERO_CTAS)

__device__ float g_A[M_ROWS * KD];           // inputs transposed [row][dim] fp32
__device__ float g_xsq[M_ROWS];
__device__ int   g_idx[M_ROWS];
__device__ uint2 g_pairs[M_ROWS * 32];       // per-row 32 (dotbits, col) pairs
__device__ __nv_bfloat16 g_Ab[M_ROWS * KD];  // bf16 copy of A
__device__ __nv_bfloat16 g_Bb[NC * KD];      // bf16 copy of codebook

// ---------------- PTX helpers (sm_80-era only; no 'a' features) ----------------
__device__ __forceinline__ uint32_t smem_u32(const void* p) {
    uint32_t a;
    asm("{ .reg .u64 t; cvta.to.shared.u64 t, %1; cvt.u32.u64 %0, t; }" : "=r"(a) : "l"(p));
    return a;
}
#define CP_ASYNC16(dst, src) \
    asm volatile("cp.async.cg.shared.global [%0], [%1], 16;" :: "r"(dst), "l"(src) : "memory")
#define CP_COMMIT() asm volatile("cp.async.commit_group;" ::: "memory")
#define CP_WAIT(n)  asm volatile("cp.async.wait_group %0;" :: "n"(n) : "memory")

__device__ __forceinline__ void ldm_x4(uint32_t* r, uint32_t addr) {
    asm volatile("ldmatrix.sync.aligned.m8n8.x4.shared.b16 {%0,%1,%2,%3}, [%4];"
                 : "=r"(r[0]), "=r"(r[1]), "=r"(r[2]), "=r"(r[3]) : "r"(addr));
}
__device__ __forceinline__ void mma16816(float* d, const uint32_t* a, const uint32_t* b) {
    asm volatile("mma.sync.aligned.m16n8k16.row.col.f32.bf16.bf16.f32 "
                 "{%0,%1,%2,%3}, {%4,%5,%6,%7}, {%8,%9}, {%0,%1,%2,%3};"
                 : "+f"(d[0]), "+f"(d[1]), "+f"(d[2]), "+f"(d[3])
                 : "r"(a[0]), "r"(a[1]), "r"(a[2]), "r"(a[3]), "r"(b[0]), "r"(b[1]));
}
// first-k MMA of a chunk: C = 0 (no acc reset needed)
__device__ __forceinline__ void mma16816_zc(float* d, const uint32_t* a, const uint32_t* b) {
    asm volatile("mma.sync.aligned.m16n8k16.row.col.f32.bf16.bf16.f32 "
                 "{%0,%1,%2,%3}, {%4,%5,%6,%7}, {%8,%9}, {%10,%11,%12,%13};"
                 : "=f"(d[0]), "=f"(d[1]), "=f"(d[2]), "=f"(d[3])
                 : "r"(a[0]), "r"(a[1]), "r"(a[2]), "r"(a[3]), "r"(b[0]), "r"(b[1]),
                   "f"(0.f), "f"(0.f), "f"(0.f), "f"(0.f));
}
__device__ __forceinline__ uint32_t swz(uint32_t byte) {
    return byte ^ ((byte >> 5) & 0x70u);
}

// ---------------- prep kernels ----------------
__global__ void k_transpose(const float* __restrict__ in) {
    __shared__ float tile[32][33];
    int b = blockIdx.z, c0 = blockIdx.y * 32, hw0 = blockIdx.x * 32;
    int tx = threadIdx.x, ty = threadIdx.y;
#pragma unroll
    for (int i = 0; i < 4; i++)
        tile[ty + i * 8][tx] = in[(b * 256 + c0 + ty + i * 8) * 1024 + hw0 + tx];
    __syncthreads();
#pragma unroll
    for (int i = 0; i < 4; i++) {
        float v = tile[tx][ty + i * 8];
        size_t o = (size_t)(b * 1024 + hw0 + ty + i * 8) * 256 + c0 + tx;
        g_A[o] = v;
        g_Ab[o] = __float2bfloat16(v);
    }
}

__global__ void k_xsq() {
    int warp = threadIdx.x >> 5, lane = threadIdx.x & 31;
    int row = blockIdx.x * 8 + warp;
    const float* p = g_A + (size_t)row * 256;
    float s = 0.f;
#pragma unroll
    for (int i = 0; i < 8; i++) { float v = p[lane + i * 32]; s = __fmaf_rn(v, v, s); }
#pragma unroll
    for (int o = 16; o; o >>= 1) s += __shfl_xor_sync(0xffffffffu, s, o);
    if (lane == 0) g_xsq[row] = s;
}

__global__ void k_bprep(const float* __restrict__ cb) {
    int t = blockIdx.x * 256 + threadIdx.x;
    float2 v = ((const float2*)cb)[t];
    __nv_bfloat162 h;
    h.x = __float2bfloat16(v.x);
    h.y = __float2bfloat16(v.y);
    ((__nv_bfloat162*)g_Bb)[t] = h;
}

// ---------------- GEMM wave: 128 GEMM CTAs + 20 one-hot zero-fill CTAs ----------------
// GEMM CTA: 512 threads (16 warps: 4m x 4n), 128 rows x 8192 cols,
// 64 chunks of 128 cols. smem: A 64KB + B 2x64KB double buffer.
// Zero CTA: streams zeros over the 537MB one-hot region with evict-first
// stores (no L2 pollution), hidden under the GEMM CTAs on the same wave.
#define SM_A  0u
#define SM_B0 65536u
#define SM_B1 131072u
#define GEMM_SMEM (196608 + 1024)

__global__ void __launch_bounds__(512, 1) k_gemm(float4* __restrict__ oh4) {
    if (blockIdx.x >= GEMM_CTAS) {
        // ---- dedicated one-hot zero-fill worker ----
        const float4 z4 = make_float4(0.f, 0.f, 0.f, 0.f);
        size_t i = (size_t)(blockIdx.x - GEMM_CTAS) * 512 + threadIdx.x;
        const size_t n4 = ONEHOT_ELEMS / 4;
        const size_t step = (size_t)ZERO_CTAS * 512;
        for (; i < n4; i += step) __stcs(oh4 + i, z4);
        return;
    }

    extern __shared__ char smem[];
    uint32_t sb = (smem_u32(smem) + 1023u) & ~1023u;
    int tid = threadIdx.x;
    int lane = tid & 31, wid = tid >> 5;
    int wm = wid & 3, wn = wid >> 2;           // 4 warps m, 4 warps n
    int m0 = blockIdx.x * 128;

    // swizzled dst offset decomposes: swz(tid*16 + i*8192) = swz(tid*16) + i*8192
    uint32_t dBase = swz((uint32_t)tid * 16u);

    // prologue: A tile + first two B chunks
    {
        const char* srcA = (const char*)(g_Ab + (size_t)m0 * KD) + tid * 16;
        const char* srcB0 = (const char*)g_Bb + tid * 16;
        const char* srcB1 = (const char*)(g_Bb + 128 * 256) + tid * 16;
#pragma unroll
        for (int i = 0; i < 8; i++)
            CP_ASYNC16(sb + SM_A + dBase + i * 8192, srcA + i * 8192);
#pragma unroll
        for (int i = 0; i < 8; i++)
            CP_ASYNC16(sb + SM_B0 + dBase + i * 8192, srcB0 + i * 8192);
        CP_COMMIT();
#pragma unroll
        for (int i = 0; i < 8; i++)
            CP_ASYNC16(sb + SM_B1 + dBase + i * 8192, srcB1 + i * 8192);
        CP_COMMIT();
    }

    int rloc0 = wm * 32 + (lane >> 2);         // CTA-local row base

    uint32_t aRow = (uint32_t)(wm * 32 + (lane & 15));
    uint32_t aXor = (aRow & 7u) << 4;
    uint32_t aCfix = (uint32_t)((lane >> 4) * 16);
    uint32_t aBase[2] = { sb + SM_A + aRow * 512, sb + SM_A + (aRow + 16) * 512 };
    uint32_t bRow = (uint32_t)(wn * 32 + ((lane >> 4) * 8) + (lane & 7));
    uint32_t bXor = (bRow & 7u) << 4;
    uint32_t bCfix = (uint32_t)(((lane >> 3) & 1) * 16);
    uint32_t bBase0 = (bRow) * 512;
    uint32_t bBase1 = (bRow + 16) * 512;

    float acc[2][4][4];

    // per-row (4 rows/thread) running max + second-max of DOT, with columns
    float m1[2][2], m2[2][2];
    int c1[2][2], c2[2][2];
#pragma unroll
    for (int mt = 0; mt < 2; mt++)
#pragma unroll
        for (int h = 0; h < 2; h++) {
            m1[mt][h] = -3.4e38f; m2[mt][h] = -3.4e38f;
            c1[mt][h] = 0; c2[mt][h] = 0;
        }

    for (int s = 0; s < 64; s++) {
        if (s < 63) CP_WAIT(1); else CP_WAIT(0);
        __syncthreads();
        uint32_t bufB = sb + ((s & 1) ? SM_B1 : SM_B0);

        // register double-buffered fragment pipeline over ks
        uint32_t fa[2][2][4], fb[2][2][4];
#pragma unroll
        for (int mt = 0; mt < 2; mt++)
            ldm_x4(fa[0][mt], aBase[mt] + ((0 + aCfix) ^ aXor));
        ldm_x4(fb[0][0], bufB + bBase0 + ((0 + bCfix) ^ bXor));
        ldm_x4(fb[0][1], bufB + bBase1 + ((0 + bCfix) ^ bXor));

#pragma unroll
        for (int ks = 0; ks < 16; ks++) {
            int cur = ks & 1, nxt = cur ^ 1;
            if (ks < 15) {
                uint32_t kb = (uint32_t)((ks + 1) * 32);
#pragma unroll
                for (int mt = 0; mt < 2; mt++)
                    ldm_x4(fa[nxt][mt], aBase[mt] + ((kb + aCfix) ^ aXor));
                ldm_x4(fb[nxt][0], bufB + bBase0 + ((kb + bCfix) ^ bXor));
                ldm_x4(fb[nxt][1], bufB + bBase1 + ((kb + bCfix) ^ bXor));
            }
            if (ks == 0) {
#pragma unroll
                for (int mt = 0; mt < 2; mt++)
#pragma unroll
                    for (int nt = 0; nt < 4; nt++)
                        mma16816_zc(acc[mt][nt], fa[cur][mt], &fb[cur][nt >> 1][(nt & 1) * 2]);
            } else {
#pragma unroll
                for (int mt = 0; mt < 2; mt++)
#pragma unroll
                    for (int nt = 0; nt < 4; nt++)
                        mma16816(acc[mt][nt], fa[cur][mt], &fb[cur][nt >> 1][(nt & 1) * 2]);
            }
        }
        __syncthreads();

        if (s + 2 < 64) {
            const char* srcB = (const char*)(g_Bb + (size_t)(s + 2) * 128 * 256) + tid * 16;
#pragma unroll
            for (int i = 0; i < 8; i++)
                CP_ASYNC16(bufB + dBase + i * 8192, srcB + i * 8192);
            CP_COMMIT();
        }

        // ---- epilogue: chunk-max prescreen, rare top-2 update, dots only ----
        int cbase = s * 128 + wn * 32 + (lane & 3) * 2;
#pragma unroll
        for (int mt = 0; mt < 2; mt++)
#pragma unroll
            for (int h = 0; h < 2; h++) {
                float gm = acc[mt][0][h * 2];
                gm = fmaxf(gm, acc[mt][0][h * 2 + 1]);
#pragma unroll
                for (int nt = 1; nt < 4; nt++) {
                    gm = fmaxf(gm, acc[mt][nt][h * 2]);
                    gm = fmaxf(gm, acc[mt][nt][h * 2 + 1]);
                }
                if (gm > m2[mt][h]) {   // rare (~13% of chunks)
#pragma unroll
                    for (int nt = 0; nt < 4; nt++) {
#pragma unroll
                        for (int e = 0; e < 2; e++) {
                            float v = acc[mt][nt][h * 2 + e];
                            int col = cbase + nt * 8 + e;
                            if (v > m1[mt][h]) {
                                m2[mt][h] = m1[mt][h]; c2[mt][h] = c1[mt][h];
                                m1[mt][h] = v;         c1[mt][h] = col;
                            } else if (v > m2[mt][h]) {
                                m2[mt][h] = v;         c2[mt][h] = col;
                            }
                        }
                    }
                }
            }
    }

    // write per-thread top-2 pairs: 32 pairs per row
    int slot = wn * 4 + (lane & 3);
#pragma unroll
    for (int mt = 0; mt < 2; mt++)
#pragma unroll
        for (int h = 0; h < 2; h++) {
            int rg = m0 + rloc0 + mt * 16 + h * 8;
            uint2 p1, p2;
            p1.x = __float_as_uint(m1[mt][h]); p1.y = (unsigned)c1[mt][h];
            p2.x = __float_as_uint(m2[mt][h]); p2.y = (unsigned)c2[mt][h];
            g_pairs[rg * 32 + slot * 2 + 0] = p1;
            g_pairs[rg * 32 + slot * 2 + 1] = p2;
        }
}

// ---------------- decide: exact rescan of near-max-dot pairs ----------------
__global__ void __launch_bounds__(256) k_decide(const float* __restrict__ cb) {
    int wid = threadIdx.x >> 5, lane = threadIdx.x & 31;
    int row = blockIdx.x * 8 + wid;
    uint2 pr = g_pairs[row * 32 + lane];
    float dot = __uint_as_float(pr.x);
    float wm = dot;
#pragma unroll
    for (int o = 16; o; o >>= 1)
        wm = fmaxf(wm, __shfl_xor_sync(0xffffffffu, wm, o));
    float thr = wm - THRD;

    unsigned long long bk = 0xffffffffffffffffull;
    if (dot >= thr) {
        const float* x = g_A + (size_t)row * 256;
        const float* cp = cb + (size_t)pr.y * 256;
        float sacc = 0.f;
        for (int k = 0; k < 256; k++) sacc = __fmaf_rn(x[k], cp[k], sacc);
        float de = __fmaf_rn(-2.f, sacc, g_xsq[row]);   // == reference fp32 dist
        bk = ((unsigned long long)__float_as_uint(de) << 32) | pr.y;
    }
#pragma unroll
    for (int o = 16; o; o >>= 1) {
        unsigned long long t2 = __shfl_xor_sync(0xffffffffu, bk, o);
        if (t2 < bk) bk = t2;
    }
    if (lane == 0) g_idx[row] = (int)(bk & 0xffffffffu);
}

// ---------------- outputs ----------------
// quant via smem transpose tile: coalesced cb reads AND coalesced BCHW writes
__global__ void __launch_bounds__(256) k_quant(const float* __restrict__ cb,
                                               float* __restrict__ out) {
    __shared__ int sidx[32];
    __shared__ float tile[32][257];
    int row0 = blockIdx.x * 32;                 // 32 rows share the same b
    int tid = threadIdx.x, lane = tid & 31, wid = tid >> 5;
    if (tid < 32) sidx[tid] = g_idx[row0 + tid];
    __syncthreads();
    for (int i = wid; i < 32; i += 8) {
        const float* cp = cb + (size_t)sidx[i] * 256;
#pragma unroll
        for (int j = 0; j < 8; j++) tile[i][lane + j * 32] = cp[lane + j * 32];
    }
    __syncthreads();
    int b = row0 >> 10, hw0 = row0 & 1023;
    float* op = out + (size_t)b * 256 * 1024 + hw0;
#pragma unroll
    for (int i = 0; i < 32; i++) {
        int d = i * 8 + wid;
        op[(size_t)d * 1024 + lane] = tile[lane][d];
    }
}

// write the 16384 ones into the pre-zeroed one_hot region
__global__ void k_scatter(float* __restrict__ oh) {
    int n = blockIdx.x * 256 + threadIdx.x;
    oh[(size_t)n * 8192 + g_idx[n]] = 1.f;
}

extern "C" void kernel_launch(void* const* d_in, const int* in_sizes, int n_in,
                              void* d_out, int out_size) {
    const float* inputs = (const float*)d_in[0];
    const float* cb     = (const float*)d_in[1];
    if (n_in >= 2 && in_sizes[0] == NC * KD && in_sizes[1] == QUANT_ELEMS) {
        inputs = (const float*)d_in[1];
        cb     = (const float*)d_in[0];
    }
    float* out = (float*)d_out;
    float* oh = out + QUANT_ELEMS;

    cudaFuncSetAttribute(k_gemm, cudaFuncAttributeMaxDynamicSharedMemorySize, GEMM_SMEM);

    k_transpose<<<dim3(32, 8, 16), dim3(32, 8)>>>(inputs);
    k_xsq<<<M_ROWS / 8, 256>>>();
    k_bprep<<<NC * KD / 2 / 256, 256>>>(cb);
    k_gemm<<<TOTAL_CTAS, 512, GEMM_SMEM>>>((float4*)oh);
    k_decide<<<M_ROWS / 8, 256>>>(cb);
    k_quant<<<M_ROWS / 32, 256>>>(cb, out);
    k_scatter<<<M_ROWS / 256, 256>>>(oh);
}

// round 12
// speedup vs baseline: 1.2786x; 1.2786x over previous
#include <cuda_runtime.h>
#include <cuda_bf16.h>
#include <cstdint>

#define M_ROWS 16384
#define KD 256
#define NC 8192
#define QUANT_ELEMS 4194304
#define ONEHOT_ELEMS 134217728
#define THRD 1.25e-4f   // candidate band in dot space (= 2.5e-4 dist / 2)
#define GEMM_CTAS 128
#define ZERO_CTAS 20
#define TOTAL_CTAS (GEMM_CTAS + ZERO_CTAS)
// one_hot float4 split: [0, DEDIC4) zeroed by workers, rest fused in GEMM loop
#define OH4_TOTAL 33554432u
#define FUSED4 8388608u                 // 128 CTAs * 64 chunks * 512 thr * 2
#define DEDIC4 (OH4_TOTAL - FUSED4)     // 25165824 (384 MB)

__device__ float g_A[M_ROWS * KD];           // inputs transposed [row][dim] fp32
__device__ float g_xsq[M_ROWS];
__device__ int   g_idx[M_ROWS];
__device__ uint2 g_pairs[M_ROWS * 32];       // per-row 32 (dotbits, col) pairs
__device__ __nv_bfloat16 g_Ab[M_ROWS * KD];  // bf16 copy of A
__device__ __nv_bfloat16 g_Bb[NC * KD];      // bf16 copy of codebook

// ---------------- PTX helpers (sm_80-era only; no 'a' features) ----------------
__device__ __forceinline__ uint32_t smem_u32(const void* p) {
    uint32_t a;
    asm("{ .reg .u64 t; cvta.to.shared.u64 t, %1; cvt.u32.u64 %0, t; }" : "=r"(a) : "l"(p));
    return a;
}
#define CP_ASYNC16(dst, src) \
    asm volatile("cp.async.cg.shared.global [%0], [%1], 16;" :: "r"(dst), "l"(src) : "memory")
#define CP_COMMIT() asm volatile("cp.async.commit_group;" ::: "memory")
#define CP_WAIT(n)  asm volatile("cp.async.wait_group %0;" :: "n"(n) : "memory")

__device__ __forceinline__ void ldm_x4(uint32_t* r, uint32_t addr) {
    asm volatile("ldmatrix.sync.aligned.m8n8.x4.shared.b16 {%0,%1,%2,%3}, [%4];"
                 : "=r"(r[0]), "=r"(r[1]), "=r"(r[2]), "=r"(r[3]) : "r"(addr));
}
__device__ __forceinline__ void mma16816(float* d, const uint32_t* a, const uint32_t* b) {
    asm volatile("mma.sync.aligned.m16n8k16.row.col.f32.bf16.bf16.f32 "
                 "{%0,%1,%2,%3}, {%4,%5,%6,%7}, {%8,%9}, {%0,%1,%2,%3};"
                 : "+f"(d[0]), "+f"(d[1]), "+f"(d[2]), "+f"(d[3])
                 : "r"(a[0]), "r"(a[1]), "r"(a[2]), "r"(a[3]), "r"(b[0]), "r"(b[1]));
}
// first-k MMA of a chunk: C = 0 (no acc reset needed)
__device__ __forceinline__ void mma16816_zc(float* d, const uint32_t* a, const uint32_t* b) {
    asm volatile("mma.sync.aligned.m16n8k16.row.col.f32.bf16.bf16.f32 "
                 "{%0,%1,%2,%3}, {%4,%5,%6,%7}, {%8,%9}, {%10,%11,%12,%13};"
                 : "=f"(d[0]), "=f"(d[1]), "=f"(d[2]), "=f"(d[3])
                 : "r"(a[0]), "r"(a[1]), "r"(a[2]), "r"(a[3]), "r"(b[0]), "r"(b[1]),
                   "f"(0.f), "f"(0.f), "f"(0.f), "f"(0.f));
}
__device__ __forceinline__ uint32_t swz(uint32_t byte) {
    return byte ^ ((byte >> 5) & 0x70u);
}

// ---------------- prep kernels ----------------
__global__ void k_transpose(const float* __restrict__ in) {
    __shared__ float tile[32][33];
    int b = blockIdx.z, c0 = blockIdx.y * 32, hw0 = blockIdx.x * 32;
    int tx = threadIdx.x, ty = threadIdx.y;
#pragma unroll
    for (int i = 0; i < 4; i++)
        tile[ty + i * 8][tx] = in[(b * 256 + c0 + ty + i * 8) * 1024 + hw0 + tx];
    __syncthreads();
#pragma unroll
    for (int i = 0; i < 4; i++) {
        float v = tile[tx][ty + i * 8];
        size_t o = (size_t)(b * 1024 + hw0 + ty + i * 8) * 256 + c0 + tx;
        g_A[o] = v;
        g_Ab[o] = __float2bfloat16(v);
    }
}

__global__ void k_xsq() {
    int warp = threadIdx.x >> 5, lane = threadIdx.x & 31;
    int row = blockIdx.x * 8 + warp;
    const float* p = g_A + (size_t)row * 256;
    float s = 0.f;
#pragma unroll
    for (int i = 0; i < 8; i++) { float v = p[lane + i * 32]; s = __fmaf_rn(v, v, s); }
#pragma unroll
    for (int o = 16; o; o >>= 1) s += __shfl_xor_sync(0xffffffffu, s, o);
    if (lane == 0) g_xsq[row] = s;
}

__global__ void k_bprep(const float* __restrict__ cb) {
    int t = blockIdx.x * 256 + threadIdx.x;
    float2 v = ((const float2*)cb)[t];
    __nv_bfloat162 h;
    h.x = __float2bfloat16(v.x);
    h.y = __float2bfloat16(v.y);
    ((__nv_bfloat162*)g_Bb)[t] = h;
}

// ---------------- GEMM wave: 128 GEMM CTAs (+ fused 128MB zero-fill)
//                  and 20 dedicated zero CTAs (384MB, evict-first) ----------------
#define SM_A  0u
#define SM_B0 65536u
#define SM_B1 131072u
#define GEMM_SMEM (196608 + 1024)

__global__ void __launch_bounds__(512, 1) k_gemm(float4* __restrict__ oh4) {
    if (blockIdx.x >= GEMM_CTAS) {
        // ---- dedicated one-hot zero-fill worker: [0, DEDIC4) ----
        const float4 z4 = make_float4(0.f, 0.f, 0.f, 0.f);
        size_t i = (size_t)(blockIdx.x - GEMM_CTAS) * 512 + threadIdx.x;
        const size_t step = (size_t)ZERO_CTAS * 512;
        for (; i < DEDIC4; i += step) __stcs(oh4 + i, z4);
        return;
    }

    extern __shared__ char smem[];
    uint32_t sb = (smem_u32(smem) + 1023u) & ~1023u;
    int tid = threadIdx.x;
    int lane = tid & 31, wid = tid >> 5;
    int wm = wid & 3, wn = wid >> 2;           // 4 warps m, 4 warps n
    int m0 = blockIdx.x * 128;

    // swizzled dst offset decomposes: swz(tid*16 + i*8192) = swz(tid*16) + i*8192
    uint32_t dBase = swz((uint32_t)tid * 16u);

    // prologue: A tile + first two B chunks
    {
        const char* srcA = (const char*)(g_Ab + (size_t)m0 * KD) + tid * 16;
        const char* srcB0 = (const char*)g_Bb + tid * 16;
        const char* srcB1 = (const char*)(g_Bb + 128 * 256) + tid * 16;
#pragma unroll
        for (int i = 0; i < 8; i++)
            CP_ASYNC16(sb + SM_A + dBase + i * 8192, srcA + i * 8192);
#pragma unroll
        for (int i = 0; i < 8; i++)
            CP_ASYNC16(sb + SM_B0 + dBase + i * 8192, srcB0 + i * 8192);
        CP_COMMIT();
#pragma unroll
        for (int i = 0; i < 8; i++)
            CP_ASYNC16(sb + SM_B1 + dBase + i * 8192, srcB1 + i * 8192);
        CP_COMMIT();
    }

    int rloc0 = wm * 32 + (lane >> 2);         // CTA-local row base

    uint32_t aRow = (uint32_t)(wm * 32 + (lane & 15));
    uint32_t aXor = (aRow & 7u) << 4;
    uint32_t aCfix = (uint32_t)((lane >> 4) * 16);
    uint32_t aBase[2] = { sb + SM_A + aRow * 512, sb + SM_A + (aRow + 16) * 512 };
    uint32_t bRow = (uint32_t)(wn * 32 + ((lane >> 4) * 8) + (lane & 7));
    uint32_t bXor = (bRow & 7u) << 4;
    uint32_t bCfix = (uint32_t)(((lane >> 3) & 1) * 16);
    uint32_t bBase0 = (bRow) * 512;
    uint32_t bBase1 = (bRow + 16) * 512;

    float acc[2][4][4];

    // per-row (4 rows/thread) running max + second-max of DOT, with columns
    float m1[2][2], m2[2][2];
    int c1[2][2], c2[2][2];
#pragma unroll
    for (int mt = 0; mt < 2; mt++)
#pragma unroll
        for (int h = 0; h < 2; h++) {
            m1[mt][h] = -3.4e38f; m2[mt][h] = -3.4e38f;
            c1[mt][h] = 0; c2[mt][h] = 0;
        }

    const float4 z4 = make_float4(0.f, 0.f, 0.f, 0.f);

    for (int s = 0; s < 64; s++) {
        if (s < 63) CP_WAIT(1); else CP_WAIT(0);
        __syncthreads();
        uint32_t bufB = sb + ((s & 1) ? SM_B1 : SM_B0);

        // register double-buffered fragment pipeline over ks
        uint32_t fa[2][2][4], fb[2][2][4];
#pragma unroll
        for (int mt = 0; mt < 2; mt++)
            ldm_x4(fa[0][mt], aBase[mt] + ((0 + aCfix) ^ aXor));
        ldm_x4(fb[0][0], bufB + bBase0 + ((0 + bCfix) ^ bXor));
        ldm_x4(fb[0][1], bufB + bBase1 + ((0 + bCfix) ^ bXor));

#pragma unroll
        for (int ks = 0; ks < 16; ks++) {
            int cur = ks & 1, nxt = cur ^ 1;
            if (ks < 15) {
                uint32_t kb = (uint32_t)((ks + 1) * 32);
#pragma unroll
                for (int mt = 0; mt < 2; mt++)
                    ldm_x4(fa[nxt][mt], aBase[mt] + ((kb + aCfix) ^ aXor));
                ldm_x4(fb[nxt][0], bufB + bBase0 + ((kb + bCfix) ^ bXor));
                ldm_x4(fb[nxt][1], bufB + bBase1 + ((kb + bCfix) ^ bXor));
            }
            if (ks == 0) {
#pragma unroll
                for (int mt = 0; mt < 2; mt++)
#pragma unroll
                    for (int nt = 0; nt < 4; nt++)
                        mma16816_zc(acc[mt][nt], fa[cur][mt], &fb[cur][nt >> 1][(nt & 1) * 2]);
            } else {
#pragma unroll
                for (int mt = 0; mt < 2; mt++)
#pragma unroll
                    for (int nt = 0; nt < 4; nt++)
                        mma16816(acc[mt][nt], fa[cur][mt], &fb[cur][nt >> 1][(nt & 1) * 2]);
            }
        }
        __syncthreads();

        if (s + 2 < 64) {
            const char* srcB = (const char*)(g_Bb + (size_t)(s + 2) * 128 * 256) + tid * 16;
#pragma unroll
            for (int i = 0; i < 8; i++)
                CP_ASYNC16(bufB + dBase + i * 8192, srcB + i * 8192);
            CP_COMMIT();
        }

        // ---- fused one-hot zero-fill share: 2 evict-first float4 stores ----
        {
            float4* zp = oh4 + DEDIC4 +
                         ((size_t)(blockIdx.x * 64 + s) * 2) * 512 + tid;
            __stcs(zp, z4);
            __stcs(zp + 512, z4);
        }

        // ---- epilogue: chunk-max prescreen, rare top-2 update, dots only ----
        int cbase = s * 128 + wn * 32 + (lane & 3) * 2;
#pragma unroll
        for (int mt = 0; mt < 2; mt++)
#pragma unroll
            for (int h = 0; h < 2; h++) {
                float gm = acc[mt][0][h * 2];
                gm = fmaxf(gm, acc[mt][0][h * 2 + 1]);
#pragma unroll
                for (int nt = 1; nt < 4; nt++) {
                    gm = fmaxf(gm, acc[mt][nt][h * 2]);
                    gm = fmaxf(gm, acc[mt][nt][h * 2 + 1]);
                }
                if (gm > m2[mt][h]) {   // rare (~13% of chunks)
#pragma unroll
                    for (int nt = 0; nt < 4; nt++) {
#pragma unroll
                        for (int e = 0; e < 2; e++) {
                            float v = acc[mt][nt][h * 2 + e];
                            int col = cbase + nt * 8 + e;
                            if (v > m1[mt][h]) {
                                m2[mt][h] = m1[mt][h]; c2[mt][h] = c1[mt][h];
                                m1[mt][h] = v;         c1[mt][h] = col;
                            } else if (v > m2[mt][h]) {
                                m2[mt][h] = v;         c2[mt][h] = col;
                            }
                        }
                    }
                }
            }
    }

    // write per-thread top-2 pairs: 32 pairs per row
    int slot = wn * 4 + (lane & 3);
#pragma unroll
    for (int mt = 0; mt < 2; mt++)
#pragma unroll
        for (int h = 0; h < 2; h++) {
            int rg = m0 + rloc0 + mt * 16 + h * 8;
            uint2 p1, p2;
            p1.x = __float_as_uint(m1[mt][h]); p1.y = (unsigned)c1[mt][h];
            p2.x = __float_as_uint(m2[mt][h]); p2.y = (unsigned)c2[mt][h];
            g_pairs[rg * 32 + slot * 2 + 0] = p1;
            g_pairs[rg * 32 + slot * 2 + 1] = p2;
        }
}

// ---------------- decide: exact rescan of near-max-dot pairs ----------------
__global__ void __launch_bounds__(256) k_decide(const float* __restrict__ cb) {
    int wid = threadIdx.x >> 5, lane = threadIdx.x & 31;
    int row = blockIdx.x * 8 + wid;
    uint2 pr = g_pairs[row * 32 + lane];
    float dot = __uint_as_float(pr.x);
    float wm = dot;
#pragma unroll
    for (int o = 16; o; o >>= 1)
        wm = fmaxf(wm, __shfl_xor_sync(0xffffffffu, wm, o));
    float thr = wm - THRD;

    unsigned long long bk = 0xffffffffffffffffull;
    if (dot >= thr) {
        const float* x = g_A + (size_t)row * 256;
        const float* cp = cb + (size_t)pr.y * 256;
        float sacc = 0.f;
        for (int k = 0; k < 256; k++) sacc = __fmaf_rn(x[k], cp[k], sacc);
        float de = __fmaf_rn(-2.f, sacc, g_xsq[row]);   // == reference fp32 dist
        bk = ((unsigned long long)__float_as_uint(de) << 32) | pr.y;
    }
#pragma unroll
    for (int o = 16; o; o >>= 1) {
        unsigned long long t2 = __shfl_xor_sync(0xffffffffu, bk, o);
        if (t2 < bk) bk = t2;
    }
    if (lane == 0) g_idx[row] = (int)(bk & 0xffffffffu);
}

// ---------------- outputs ----------------
// quant via smem transpose tile: coalesced cb reads AND coalesced BCHW writes
__global__ void __launch_bounds__(256) k_quant(const float* __restrict__ cb,
                                               float* __restrict__ out) {
    __shared__ int sidx[32];
    __shared__ float tile[32][257];
    int row0 = blockIdx.x * 32;                 // 32 rows share the same b
    int tid = threadIdx.x, lane = tid & 31, wid = tid >> 5;
    if (tid < 32) sidx[tid] = g_idx[row0 + tid];
    __syncthreads();
    for (int i = wid; i < 32; i += 8) {
        const float* cp = cb + (size_t)sidx[i] * 256;
#pragma unroll
        for (int j = 0; j < 8; j++) tile[i][lane + j * 32] = cp[lane + j * 32];
    }
    __syncthreads();
    int b = row0 >> 10, hw0 = row0 & 1023;
    float* op = out + (size_t)b * 256 * 1024 + hw0;
#pragma unroll
    for (int i = 0; i < 32; i++) {
        int d = i * 8 + wid;
        op[(size_t)d * 1024 + lane] = tile[lane][d];
    }
}

// write the 16384 ones into the pre-zeroed one_hot region
__global__ void k_scatter(float* __restrict__ oh) {
    int n = blockIdx.x * 256 + threadIdx.x;
    oh[(size_t)n * 8192 + g_idx[n]] = 1.f;
}

extern "C" void kernel_launch(void* const* d_in, const int* in_sizes, int n_in,
                              void* d_out, int out_size) {
    const float* inputs = (const float*)d_in[0];
    const float* cb     = (const float*)d_in[1];
    if (n_in >= 2 && in_sizes[0] == NC * KD && in_sizes[1] == QUANT_ELEMS) {
        inputs = (const float*)d_in[1];
        cb     = (const float*)d_in[0];
    }
    float* out = (float*)d_out;
    float* oh = out + QUANT_ELEMS;

    cudaFuncSetAttribute(k_gemm, cudaFuncAttributeMaxDynamicSharedMemorySize, GEMM_SMEM);

    k_transpose<<<dim3(32, 8, 16), dim3(32, 8)>>>(inputs);
    k_xsq<<<M_ROWS / 8, 256>>>();
    k_bprep<<<NC * KD / 2 / 256, 256>>>(cb);
    k_gemm<<<TOTAL_CTAS, 512, GEMM_SMEM>>>((float4*)oh);
    k_decide<<<M_ROWS / 8, 256>>>(cb);
    k_quant<<<M_ROWS / 32, 256>>>(cb, out);
    k_scatter<<<M_ROWS / 256, 256>>>(oh);
}

// round 13
// speedup vs baseline: 1.4449x; 1.1301x over previous
#include <cuda_runtime.h>
#include <cuda_bf16.h>
#include <cstdint>

#define M_ROWS 16384
#define KD 256
#define NC 8192
#define QUANT_ELEMS 4194304
#define ONEHOT_ELEMS 134217728
#define THRD 1.25e-4f   // candidate band in dot space (= 2.5e-4 dist / 2)

__device__ float g_A[M_ROWS * KD];           // inputs transposed [row][dim] fp32
__device__ float g_xsq[M_ROWS];
__device__ int   g_idx[M_ROWS];
__device__ uint2 g_pairs[M_ROWS * 32];       // per-row 32 (dotbits, col) pairs
__device__ __nv_bfloat16 g_Ab[M_ROWS * KD];  // bf16 copy of A
__device__ __nv_bfloat16 g_Bb[NC * KD];      // bf16 copy of codebook

// ---------------- PTX helpers (sm_80-era only; no 'a' features) ----------------
__device__ __forceinline__ uint32_t smem_u32(const void* p) {
    uint32_t a;
    asm("{ .reg .u64 t; cvta.to.shared.u64 t, %1; cvt.u32.u64 %0, t; }" : "=r"(a) : "l"(p));
    return a;
}
#define CP_ASYNC16(dst, src) \
    asm volatile("cp.async.cg.shared.global [%0], [%1], 16;" :: "r"(dst), "l"(src) : "memory")
#define CP_COMMIT() asm volatile("cp.async.commit_group;" ::: "memory")
#define CP_WAIT(n)  asm volatile("cp.async.wait_group %0;" :: "n"(n) : "memory")

__device__ __forceinline__ void ldm_x4(uint32_t* r, uint32_t addr) {
    asm volatile("ldmatrix.sync.aligned.m8n8.x4.shared.b16 {%0,%1,%2,%3}, [%4];"
                 : "=r"(r[0]), "=r"(r[1]), "=r"(r[2]), "=r"(r[3]) : "r"(addr));
}
__device__ __forceinline__ void mma16816(float* d, const uint32_t* a, const uint32_t* b) {
    asm volatile("mma.sync.aligned.m16n8k16.row.col.f32.bf16.bf16.f32 "
                 "{%0,%1,%2,%3}, {%4,%5,%6,%7}, {%8,%9}, {%0,%1,%2,%3};"
                 : "+f"(d[0]), "+f"(d[1]), "+f"(d[2]), "+f"(d[3])
                 : "r"(a[0]), "r"(a[1]), "r"(a[2]), "r"(a[3]), "r"(b[0]), "r"(b[1]));
}
// first-k MMA of a chunk: C = 0 (no acc reset needed)
__device__ __forceinline__ void mma16816_zc(float* d, const uint32_t* a, const uint32_t* b) {
    asm volatile("mma.sync.aligned.m16n8k16.row.col.f32.bf16.bf16.f32 "
                 "{%0,%1,%2,%3}, {%4,%5,%6,%7}, {%8,%9}, {%10,%11,%12,%13};"
                 : "=f"(d[0]), "=f"(d[1]), "=f"(d[2]), "=f"(d[3])
                 : "r"(a[0]), "r"(a[1]), "r"(a[2]), "r"(a[3]), "r"(b[0]), "r"(b[1]),
                   "f"(0.f), "f"(0.f), "f"(0.f), "f"(0.f));
}
__device__ __forceinline__ uint32_t swz(uint32_t byte) {
    return byte ^ ((byte >> 5) & 0x70u);
}

// ---------------- prep kernels ----------------
__global__ void k_transpose(const float* __restrict__ in) {
    __shared__ float tile[32][33];
    int b = blockIdx.z, c0 = blockIdx.y * 32, hw0 = blockIdx.x * 32;
    int tx = threadIdx.x, ty = threadIdx.y;
#pragma unroll
    for (int i = 0; i < 4; i++)
        tile[ty + i * 8][tx] = in[(b * 256 + c0 + ty + i * 8) * 1024 + hw0 + tx];
    __syncthreads();
#pragma unroll
    for (int i = 0; i < 4; i++) {
        float v = tile[tx][ty + i * 8];
        size_t o = (size_t)(b * 1024 + hw0 + ty + i * 8) * 256 + c0 + tx;
        g_A[o] = v;
        g_Ab[o] = __float2bfloat16(v);
    }
}

__global__ void k_xsq() {
    int warp = threadIdx.x >> 5, lane = threadIdx.x & 31;
    int row = blockIdx.x * 8 + warp;
    const float* p = g_A + (size_t)row * 256;
    float s = 0.f;
#pragma unroll
    for (int i = 0; i < 8; i++) { float v = p[lane + i * 32]; s = __fmaf_rn(v, v, s); }
#pragma unroll
    for (int o = 16; o; o >>= 1) s += __shfl_xor_sync(0xffffffffu, s, o);
    if (lane == 0) g_xsq[row] = s;
}

__global__ void k_bprep(const float* __restrict__ cb) {
    int t = blockIdx.x * 256 + threadIdx.x;
    float2 v = ((const float2*)cb)[t];
    __nv_bfloat162 h;
    h.x = __float2bfloat16(v.x);
    h.y = __float2bfloat16(v.y);
    ((__nv_bfloat162*)g_Bb)[t] = h;
}

// ---------------- GEMM + top-2 dots + spread one-hot zero-fill ----------------
// 128 CTAs, 512 threads (16 warps: 4m x 4n). CTA = 128 rows x 8192 cols,
// 64 chunks of 128 cols. smem: A 64KB + B 2x64KB double buffer.
// One-hot zero-fill (512MB total) is spread INSIDE the ks loop: one evict-
// first float4 store every 2 ks steps (8 per chunk), filling LSU issue gaps
// between ldmatrix bursts instead of jamming at the chunk boundary.
#define SM_A  0u
#define SM_B0 65536u
#define SM_B1 131072u
#define GEMM_SMEM (196608 + 1024)

__global__ void __launch_bounds__(512, 1) k_gemm(float4* __restrict__ oh4) {
    extern __shared__ char smem[];
    uint32_t sb = (smem_u32(smem) + 1023u) & ~1023u;
    int tid = threadIdx.x;
    int lane = tid & 31, wid = tid >> 5;
    int wm = wid & 3, wn = wid >> 2;           // 4 warps m, 4 warps n
    int m0 = blockIdx.x * 128;

    // swizzled dst offset decomposes: swz(tid*16 + i*8192) = swz(tid*16) + i*8192
    uint32_t dBase = swz((uint32_t)tid * 16u);

    // prologue: A tile + first two B chunks
    {
        const char* srcA = (const char*)(g_Ab + (size_t)m0 * KD) + tid * 16;
        const char* srcB0 = (const char*)g_Bb + tid * 16;
        const char* srcB1 = (const char*)(g_Bb + 128 * 256) + tid * 16;
#pragma unroll
        for (int i = 0; i < 8; i++)
            CP_ASYNC16(sb + SM_A + dBase + i * 8192, srcA + i * 8192);
#pragma unroll
        for (int i = 0; i < 8; i++)
            CP_ASYNC16(sb + SM_B0 + dBase + i * 8192, srcB0 + i * 8192);
        CP_COMMIT();
#pragma unroll
        for (int i = 0; i < 8; i++)
            CP_ASYNC16(sb + SM_B1 + dBase + i * 8192, srcB1 + i * 8192);
        CP_COMMIT();
    }

    int rloc0 = wm * 32 + (lane >> 2);         // CTA-local row base

    uint32_t aRow = (uint32_t)(wm * 32 + (lane & 15));
    uint32_t aXor = (aRow & 7u) << 4;
    uint32_t aCfix = (uint32_t)((lane >> 4) * 16);
    uint32_t aBase[2] = { sb + SM_A + aRow * 512, sb + SM_A + (aRow + 16) * 512 };
    uint32_t bRow = (uint32_t)(wn * 32 + ((lane >> 4) * 8) + (lane & 7));
    uint32_t bXor = (bRow & 7u) << 4;
    uint32_t bCfix = (uint32_t)(((lane >> 3) & 1) * 16);
    uint32_t bBase0 = (bRow) * 512;
    uint32_t bBase1 = (bRow + 16) * 512;

    float acc[2][4][4];

    // per-row (4 rows/thread) running max + second-max of DOT, with columns
    float m1[2][2], m2[2][2];
    int c1[2][2], c2[2][2];
#pragma unroll
    for (int mt = 0; mt < 2; mt++)
#pragma unroll
        for (int h = 0; h < 2; h++) {
            m1[mt][h] = -3.4e38f; m2[mt][h] = -3.4e38f;
            c1[mt][h] = 0; c2[mt][h] = 0;
        }

    const float4 z4 = make_float4(0.f, 0.f, 0.f, 0.f);

    for (int s = 0; s < 64; s++) {
        if (s < 63) CP_WAIT(1); else CP_WAIT(0);
        __syncthreads();
        uint32_t bufB = sb + ((s & 1) ? SM_B1 : SM_B0);
        float4* zp = oh4 + ((size_t)(blockIdx.x * 64 + s) * 8) * 512 + tid;

        // register double-buffered fragment pipeline over ks
        uint32_t fa[2][2][4], fb[2][2][4];
#pragma unroll
        for (int mt = 0; mt < 2; mt++)
            ldm_x4(fa[0][mt], aBase[mt] + ((0 + aCfix) ^ aXor));
        ldm_x4(fb[0][0], bufB + bBase0 + ((0 + bCfix) ^ bXor));
        ldm_x4(fb[0][1], bufB + bBase1 + ((0 + bCfix) ^ bXor));

#pragma unroll
        for (int ks = 0; ks < 16; ks++) {
            int cur = ks & 1, nxt = cur ^ 1;
            if (ks < 15) {
                uint32_t kb = (uint32_t)((ks + 1) * 32);
#pragma unroll
                for (int mt = 0; mt < 2; mt++)
                    ldm_x4(fa[nxt][mt], aBase[mt] + ((kb + aCfix) ^ aXor));
                ldm_x4(fb[nxt][0], bufB + bBase0 + ((kb + bCfix) ^ bXor));
                ldm_x4(fb[nxt][1], bufB + bBase1 + ((kb + bCfix) ^ bXor));
            }
            // spread one-hot zero-fill: one evict-first store every 2 ks
            if ((ks & 1) == 0) __stcs(zp + (ks >> 1) * 512, z4);
            if (ks == 0) {
#pragma unroll
                for (int mt = 0; mt < 2; mt++)
#pragma unroll
                    for (int nt = 0; nt < 4; nt++)
                        mma16816_zc(acc[mt][nt], fa[cur][mt], &fb[cur][nt >> 1][(nt & 1) * 2]);
            } else {
#pragma unroll
                for (int mt = 0; mt < 2; mt++)
#pragma unroll
                    for (int nt = 0; nt < 4; nt++)
                        mma16816(acc[mt][nt], fa[cur][mt], &fb[cur][nt >> 1][(nt & 1) * 2]);
            }
        }
        __syncthreads();

        if (s + 2 < 64) {
            const char* srcB = (const char*)(g_Bb + (size_t)(s + 2) * 128 * 256) + tid * 16;
#pragma unroll
            for (int i = 0; i < 8; i++)
                CP_ASYNC16(bufB + dBase + i * 8192, srcB + i * 8192);
            CP_COMMIT();
        }

        // ---- epilogue: chunk-max prescreen, rare top-2 update, dots only ----
        int cbase = s * 128 + wn * 32 + (lane & 3) * 2;
#pragma unroll
        for (int mt = 0; mt < 2; mt++)
#pragma unroll
            for (int h = 0; h < 2; h++) {
                float gm = acc[mt][0][h * 2];
                gm = fmaxf(gm, acc[mt][0][h * 2 + 1]);
#pragma unroll
                for (int nt = 1; nt < 4; nt++) {
                    gm = fmaxf(gm, acc[mt][nt][h * 2]);
                    gm = fmaxf(gm, acc[mt][nt][h * 2 + 1]);
                }
                if (gm > m2[mt][h]) {   // rare (~13% of chunks)
#pragma unroll
                    for (int nt = 0; nt < 4; nt++) {
#pragma unroll
                        for (int e = 0; e < 2; e++) {
                            float v = acc[mt][nt][h * 2 + e];
                            int col = cbase + nt * 8 + e;
                            if (v > m1[mt][h]) {
                                m2[mt][h] = m1[mt][h]; c2[mt][h] = c1[mt][h];
                                m1[mt][h] = v;         c1[mt][h] = col;
                            } else if (v > m2[mt][h]) {
                                m2[mt][h] = v;         c2[mt][h] = col;
                            }
                        }
                    }
                }
            }
    }

    // write per-thread top-2 pairs: 32 pairs per row
    int slot = wn * 4 + (lane & 3);
#pragma unroll
    for (int mt = 0; mt < 2; mt++)
#pragma unroll
        for (int h = 0; h < 2; h++) {
            int rg = m0 + rloc0 + mt * 16 + h * 8;
            uint2 p1, p2;
            p1.x = __float_as_uint(m1[mt][h]); p1.y = (unsigned)c1[mt][h];
            p2.x = __float_as_uint(m2[mt][h]); p2.y = (unsigned)c2[mt][h];
            g_pairs[rg * 32 + slot * 2 + 0] = p1;
            g_pairs[rg * 32 + slot * 2 + 1] = p2;
        }
}

// ---------------- decide + one-hot scatter (zeros already written) ----------------
__global__ void __launch_bounds__(256) k_decide(const float* __restrict__ cb,
                                                float* __restrict__ oh) {
    int wid = threadIdx.x >> 5, lane = threadIdx.x & 31;
    int row = blockIdx.x * 8 + wid;
    uint2 pr = g_pairs[row * 32 + lane];
    float dot = __uint_as_float(pr.x);
    float wm = dot;
#pragma unroll
    for (int o = 16; o; o >>= 1)
        wm = fmaxf(wm, __shfl_xor_sync(0xffffffffu, wm, o));
    float thr = wm - THRD;

    unsigned long long bk = 0xffffffffffffffffull;
    if (dot >= thr) {
        const float* x = g_A + (size_t)row * 256;
        const float* cp = cb + (size_t)pr.y * 256;
        float sacc = 0.f;
        for (int k = 0; k < 256; k++) sacc = __fmaf_rn(x[k], cp[k], sacc);
        float de = __fmaf_rn(-2.f, sacc, g_xsq[row]);   // == reference fp32 dist
        bk = ((unsigned long long)__float_as_uint(de) << 32) | pr.y;
    }
#pragma unroll
    for (int o = 16; o; o >>= 1) {
        unsigned long long t2 = __shfl_xor_sync(0xffffffffu, bk, o);
        if (t2 < bk) bk = t2;
    }
    if (lane == 0) {
        int idx = (int)(bk & 0xffffffffu);
        g_idx[row] = idx;
        oh[(size_t)row * 8192 + idx] = 1.f;   // scatter the one
    }
}

// ---------------- quantized output ----------------
// quant via smem transpose tile: coalesced cb reads AND coalesced BCHW writes
__global__ void __launch_bounds__(256) k_quant(const float* __restrict__ cb,
                                               float* __restrict__ out) {
    __shared__ int sidx[32];
    __shared__ float tile[32][257];
    int row0 = blockIdx.x * 32;                 // 32 rows share the same b
    int tid = threadIdx.x, lane = tid & 31, wid = tid >> 5;
    if (tid < 32) sidx[tid] = g_idx[row0 + tid];
    __syncthreads();
    for (int i = wid; i < 32; i += 8) {
        const float* cp = cb + (size_t)sidx[i] * 256;
#pragma unroll
        for (int j = 0; j < 8; j++) tile[i][lane + j * 32] = cp[lane + j * 32];
    }
    __syncthreads();
    int b = row0 >> 10, hw0 = row0 & 1023;
    float* op = out + (size_t)b * 256 * 1024 + hw0;
#pragma unroll
    for (int i = 0; i < 32; i++) {
        int d = i * 8 + wid;
        op[(size_t)d * 1024 + lane] = tile[lane][d];
    }
}

extern "C" void kernel_launch(void* const* d_in, const int* in_sizes, int n_in,
                              void* d_out, int out_size) {
    const float* inputs = (const float*)d_in[0];
    const float* cb     = (const float*)d_in[1];
    if (n_in >= 2 && in_sizes[0] == NC * KD && in_sizes[1] == QUANT_ELEMS) {
        inputs = (const float*)d_in[1];
        cb     = (const float*)d_in[0];
    }
    float* out = (float*)d_out;
    float* oh = out + QUANT_ELEMS;

    cudaFuncSetAttribute(k_gemm, cudaFuncAttributeMaxDynamicSharedMemorySize, GEMM_SMEM);

    k_transpose<<<dim3(32, 8, 16), dim3(32, 8)>>>(inputs);
    k_xsq<<<M_ROWS / 8, 256>>>();
    k_bprep<<<NC * KD / 2 / 256, 256>>>(cb);
    k_gemm<<<128, 512, GEMM_SMEM>>>((float4*)oh);
    k_decide<<<M_ROWS / 8, 256>>>(cb, oh);
    k_quant<<<M_ROWS / 32, 256>>>(cb, out);
}

// round 14
// speedup vs baseline: 1.5756x; 1.0904x over previous
#include <cuda_runtime.h>
#include <cuda_bf16.h>
#include <cstdint>

#define M_ROWS 16384
#define KD 256
#define NC 8192
#define QUANT_ELEMS 4194304
#define ONEHOT_ELEMS 134217728
#define THRD 1.25e-4f   // candidate band in dot space (= 2.5e-4 dist / 2)

__device__ float g_A[M_ROWS * KD];           // inputs transposed [row][dim] fp32
__device__ float g_xsq[M_ROWS];
__device__ int   g_idx[M_ROWS];
__device__ uint2 g_pairs[M_ROWS * 32];       // per-row 32 (dotbits, col) pairs
__device__ __nv_bfloat16 g_Ab[M_ROWS * KD];  // bf16 copy of A
__device__ __nv_bfloat16 g_Bb[NC * KD];      // bf16 copy of codebook

// ---------------- PTX helpers (sm_80/90 era only; no 'a' features) ----------------
__device__ __forceinline__ uint32_t smem_u32(const void* p) {
    uint32_t a;
    asm("{ .reg .u64 t; cvta.to.shared.u64 t, %1; cvt.u32.u64 %0, t; }" : "=r"(a) : "l"(p));
    return a;
}
#define CP_ASYNC16(dst, src) \
    asm volatile("cp.async.cg.shared.global [%0], [%1], 16;" :: "r"(dst), "l"(src) : "memory")
#define CP_COMMIT() asm volatile("cp.async.commit_group;" ::: "memory")
#define CP_WAIT(n)  asm volatile("cp.async.wait_group %0;" :: "n"(n) : "memory")

// bulk S2G copy (plain cp.async.bulk, sm_90 PTX, not 'a'-gated)
#define BULK_S2G(gdst, ssrc, bytes) \
    asm volatile("cp.async.bulk.global.shared::cta.bulk_group [%0], [%1], %2;" \
                 :: "l"(gdst), "r"(ssrc), "r"(bytes) : "memory")
#define BULK_COMMIT() asm volatile("cp.async.bulk.commit_group;" ::: "memory")
#define BULK_WAIT0()  asm volatile("cp.async.bulk.wait_group 0;" ::: "memory")
#define FENCE_PROXY_ASYNC() asm volatile("fence.proxy.async.shared::cta;" ::: "memory")

__device__ __forceinline__ void ldm_x4(uint32_t* r, uint32_t addr) {
    asm volatile("ldmatrix.sync.aligned.m8n8.x4.shared.b16 {%0,%1,%2,%3}, [%4];"
                 : "=r"(r[0]), "=r"(r[1]), "=r"(r[2]), "=r"(r[3]) : "r"(addr));
}
__device__ __forceinline__ void mma16816(float* d, const uint32_t* a, const uint32_t* b) {
    asm volatile("mma.sync.aligned.m16n8k16.row.col.f32.bf16.bf16.f32 "
                 "{%0,%1,%2,%3}, {%4,%5,%6,%7}, {%8,%9}, {%0,%1,%2,%3};"
                 : "+f"(d[0]), "+f"(d[1]), "+f"(d[2]), "+f"(d[3])
                 : "r"(a[0]), "r"(a[1]), "r"(a[2]), "r"(a[3]), "r"(b[0]), "r"(b[1]));
}
// first-k MMA of a chunk: C = 0 (no acc reset needed)
__device__ __forceinline__ void mma16816_zc(float* d, const uint32_t* a, const uint32_t* b) {
    asm volatile("mma.sync.aligned.m16n8k16.row.col.f32.bf16.bf16.f32 "
                 "{%0,%1,%2,%3}, {%4,%5,%6,%7}, {%8,%9}, {%10,%11,%12,%13};"
                 : "=f"(d[0]), "=f"(d[1]), "=f"(d[2]), "=f"(d[3])
                 : "r"(a[0]), "r"(a[1]), "r"(a[2]), "r"(a[3]), "r"(b[0]), "r"(b[1]),
                   "f"(0.f), "f"(0.f), "f"(0.f), "f"(0.f));
}
__device__ __forceinline__ uint32_t swz(uint32_t byte) {
    return byte ^ ((byte >> 5) & 0x70u);
}

// ---------------- prep kernels ----------------
__global__ void k_transpose(const float* __restrict__ in) {
    __shared__ float tile[32][33];
    int b = blockIdx.z, c0 = blockIdx.y * 32, hw0 = blockIdx.x * 32;
    int tx = threadIdx.x, ty = threadIdx.y;
#pragma unroll
    for (int i = 0; i < 4; i++)
        tile[ty + i * 8][tx] = in[(b * 256 + c0 + ty + i * 8) * 1024 + hw0 + tx];
    __syncthreads();
#pragma unroll
    for (int i = 0; i < 4; i++) {
        float v = tile[tx][ty + i * 8];
        size_t o = (size_t)(b * 1024 + hw0 + ty + i * 8) * 256 + c0 + tx;
        g_A[o] = v;
        g_Ab[o] = __float2bfloat16(v);
    }
}

__global__ void k_xsq() {
    int warp = threadIdx.x >> 5, lane = threadIdx.x & 31;
    int row = blockIdx.x * 8 + warp;
    const float* p = g_A + (size_t)row * 256;
    float s = 0.f;
#pragma unroll
    for (int i = 0; i < 8; i++) { float v = p[lane + i * 32]; s = __fmaf_rn(v, v, s); }
#pragma unroll
    for (int o = 16; o; o >>= 1) s += __shfl_xor_sync(0xffffffffu, s, o);
    if (lane == 0) g_xsq[row] = s;
}

__global__ void k_bprep(const float* __restrict__ cb) {
    int t = blockIdx.x * 256 + threadIdx.x;
    float2 v = ((const float2*)cb)[t];
    __nv_bfloat162 h;
    h.x = __float2bfloat16(v.x);
    h.y = __float2bfloat16(v.y);
    ((__nv_bfloat162*)g_Bb)[t] = h;
}

// ---------------- GEMM + top-2 dots + bulk-engine one-hot zero-fill ----------------
// 128 CTAs, 512 threads (16 warps: 4m x 4n). CTA = 128 rows x 8192 cols,
// 64 chunks of 128 cols. smem: A 64KB + B 2x64KB double buffer + 16KB zeros.
// One-hot zeroing (512MB) rides the bulk-copy engine: thread 0 issues 4x16KB
// cp.async.bulk S2G per chunk from the zeroed smem buffer — no LSU/STG cost.
#define SM_A  0u
#define SM_B0 65536u
#define SM_B1 131072u
#define SM_ZERO 196608u
#define GEMM_SMEM (196608 + 16384 + 1024)

__global__ void __launch_bounds__(512, 1) k_gemm(char* __restrict__ ohb) {
    extern __shared__ char smem[];
    uint32_t sbr = smem_u32(smem);
    uint32_t sb = (sbr + 1023u) & ~1023u;
    char* smem_al = smem + (sb - sbr);
    int tid = threadIdx.x;
    int lane = tid & 31, wid = tid >> 5;
    int wm = wid & 3, wn = wid >> 2;           // 4 warps m, 4 warps n
    int m0 = blockIdx.x * 128;

    // zero the bulk-source buffer (16KB)
    {
        float4 z4 = make_float4(0.f, 0.f, 0.f, 0.f);
        float4* z = (float4*)(smem_al + SM_ZERO);
        z[tid] = z4;
        z[tid + 512] = z4;
    }

    // swizzled dst offset decomposes: swz(tid*16 + i*8192) = swz(tid*16) + i*8192
    uint32_t dBase = swz((uint32_t)tid * 16u);

    // prologue: A tile + first two B chunks
    {
        const char* srcA = (const char*)(g_Ab + (size_t)m0 * KD) + tid * 16;
        const char* srcB0 = (const char*)g_Bb + tid * 16;
        const char* srcB1 = (const char*)(g_Bb + 128 * 256) + tid * 16;
#pragma unroll
        for (int i = 0; i < 8; i++)
            CP_ASYNC16(sb + SM_A + dBase + i * 8192, srcA + i * 8192);
#pragma unroll
        for (int i = 0; i < 8; i++)
            CP_ASYNC16(sb + SM_B0 + dBase + i * 8192, srcB0 + i * 8192);
        CP_COMMIT();
#pragma unroll
        for (int i = 0; i < 8; i++)
            CP_ASYNC16(sb + SM_B1 + dBase + i * 8192, srcB1 + i * 8192);
        CP_COMMIT();
    }

    // make the zero buffer visible to the async (bulk) proxy
    __syncthreads();
    if (tid == 0) FENCE_PROXY_ASYNC();
    __syncthreads();

    int rloc0 = wm * 32 + (lane >> 2);         // CTA-local row base

    uint32_t aRow = (uint32_t)(wm * 32 + (lane & 15));
    uint32_t aXor = (aRow & 7u) << 4;
    uint32_t aCfix = (uint32_t)((lane >> 4) * 16);
    uint32_t aBase[2] = { sb + SM_A + aRow * 512, sb + SM_A + (aRow + 16) * 512 };
    uint32_t bRow = (uint32_t)(wn * 32 + ((lane >> 4) * 8) + (lane & 7));
    uint32_t bXor = (bRow & 7u) << 4;
    uint32_t bCfix = (uint32_t)(((lane >> 3) & 1) * 16);
    uint32_t bBase0 = (bRow) * 512;
    uint32_t bBase1 = (bRow + 16) * 512;

    float acc[2][4][4];

    // per-row (4 rows/thread) running max + second-max of DOT, with columns
    float m1[2][2], m2[2][2];
    int c1[2][2], c2[2][2];
#pragma unroll
    for (int mt = 0; mt < 2; mt++)
#pragma unroll
        for (int h = 0; h < 2; h++) {
            m1[mt][h] = -3.4e38f; m2[mt][h] = -3.4e38f;
            c1[mt][h] = 0; c2[mt][h] = 0;
        }

    for (int s = 0; s < 64; s++) {
        if (s < 63) CP_WAIT(1); else CP_WAIT(0);
        __syncthreads();
        uint32_t bufB = sb + ((s & 1) ? SM_B1 : SM_B0);

        // one-hot zero-fill via bulk engine: 64KB per chunk, zero LSU cost
        if (tid == 0) {
            char* gd = ohb + ((size_t)(blockIdx.x * 64 + s) << 16);
#pragma unroll
            for (int i = 0; i < 4; i++)
                BULK_S2G(gd + i * 16384, sb + SM_ZERO, 16384u);
            BULK_COMMIT();
        }

        // register double-buffered fragment pipeline over ks
        uint32_t fa[2][2][4], fb[2][2][4];
#pragma unroll
        for (int mt = 0; mt < 2; mt++)
            ldm_x4(fa[0][mt], aBase[mt] + ((0 + aCfix) ^ aXor));
        ldm_x4(fb[0][0], bufB + bBase0 + ((0 + bCfix) ^ bXor));
        ldm_x4(fb[0][1], bufB + bBase1 + ((0 + bCfix) ^ bXor));

#pragma unroll
        for (int ks = 0; ks < 16; ks++) {
            int cur = ks & 1, nxt = cur ^ 1;
            if (ks < 15) {
                uint32_t kb = (uint32_t)((ks + 1) * 32);
#pragma unroll
                for (int mt = 0; mt < 2; mt++)
                    ldm_x4(fa[nxt][mt], aBase[mt] + ((kb + aCfix) ^ aXor));
                ldm_x4(fb[nxt][0], bufB + bBase0 + ((kb + bCfix) ^ bXor));
                ldm_x4(fb[nxt][1], bufB + bBase1 + ((kb + bCfix) ^ bXor));
            }
            if (ks == 0) {
#pragma unroll
                for (int mt = 0; mt < 2; mt++)
#pragma unroll
                    for (int nt = 0; nt < 4; nt++)
                        mma16816_zc(acc[mt][nt], fa[cur][mt], &fb[cur][nt >> 1][(nt & 1) * 2]);
            } else {
#pragma unroll
                for (int mt = 0; mt < 2; mt++)
#pragma unroll
                    for (int nt = 0; nt < 4; nt++)
                        mma16816(acc[mt][nt], fa[cur][mt], &fb[cur][nt >> 1][(nt & 1) * 2]);
            }
        }
        __syncthreads();

        if (s + 2 < 64) {
            const char* srcB = (const char*)(g_Bb + (size_t)(s + 2) * 128 * 256) + tid * 16;
#pragma unroll
            for (int i = 0; i < 8; i++)
                CP_ASYNC16(bufB + dBase + i * 8192, srcB + i * 8192);
            CP_COMMIT();
        }

        // ---- epilogue: chunk-max prescreen, rare top-2 update, dots only ----
        int cbase = s * 128 + wn * 32 + (lane & 3) * 2;
#pragma unroll
        for (int mt = 0; mt < 2; mt++)
#pragma unroll
            for (int h = 0; h < 2; h++) {
                float gm = acc[mt][0][h * 2];
                gm = fmaxf(gm, acc[mt][0][h * 2 + 1]);
#pragma unroll
                for (int nt = 1; nt < 4; nt++) {
                    gm = fmaxf(gm, acc[mt][nt][h * 2]);
                    gm = fmaxf(gm, acc[mt][nt][h * 2 + 1]);
                }
                if (gm > m2[mt][h]) {   // rare (~13% of chunks)
#pragma unroll
                    for (int nt = 0; nt < 4; nt++) {
#pragma unroll
                        for (int e = 0; e < 2; e++) {
                            float v = acc[mt][nt][h * 2 + e];
                            int col = cbase + nt * 8 + e;
                            if (v > m1[mt][h]) {
                                m2[mt][h] = m1[mt][h]; c2[mt][h] = c1[mt][h];
                                m1[mt][h] = v;         c1[mt][h] = col;
                            } else if (v > m2[mt][h]) {
                                m2[mt][h] = v;         c2[mt][h] = col;
                            }
                        }
                    }
                }
            }
    }

    // write per-thread top-2 pairs: 32 pairs per row
    int slot = wn * 4 + (lane & 3);
#pragma unroll
    for (int mt = 0; mt < 2; mt++)
#pragma unroll
        for (int h = 0; h < 2; h++) {
            int rg = m0 + rloc0 + mt * 16 + h * 8;
            uint2 p1, p2;
            p1.x = __float_as_uint(m1[mt][h]); p1.y = (unsigned)c1[mt][h];
            p2.x = __float_as_uint(m2[mt][h]); p2.y = (unsigned)c2[mt][h];
            g_pairs[rg * 32 + slot * 2 + 0] = p1;
            g_pairs[rg * 32 + slot * 2 + 1] = p2;
        }

    // drain outstanding bulk zero-fill before kernel end
    if (tid == 0) BULK_WAIT0();
}

// ---------------- decide + one-hot scatter (zeros already written) ----------------
__global__ void __launch_bounds__(256) k_decide(const float* __restrict__ cb,
                                                float* __restrict__ oh) {
    int wid = threadIdx.x >> 5, lane = threadIdx.x & 31;
    int row = blockIdx.x * 8 + wid;
    uint2 pr = g_pairs[row * 32 + lane];
    float dot = __uint_as_float(pr.x);
    float wm = dot;
#pragma unroll
    for (int o = 16; o; o >>= 1)
        wm = fmaxf(wm, __shfl_xor_sync(0xffffffffu, wm, o));
    float thr = wm - THRD;

    unsigned long long bk = 0xffffffffffffffffull;
    if (dot >= thr) {
        const float* x = g_A + (size_t)row * 256;
        const float* cp = cb + (size_t)pr.y * 256;
        float sacc = 0.f;
        for (int k = 0; k < 256; k++) sacc = __fmaf_rn(x[k], cp[k], sacc);
        float de = __fmaf_rn(-2.f, sacc, g_xsq[row]);   // == reference fp32 dist
        bk = ((unsigned long long)__float_as_uint(de) << 32) | pr.y;
    }
#pragma unroll
    for (int o = 16; o; o >>= 1) {
        unsigned long long t2 = __shfl_xor_sync(0xffffffffu, bk, o);
        if (t2 < bk) bk = t2;
    }
    if (lane == 0) {
        int idx = (int)(bk & 0xffffffffu);
        g_idx[row] = idx;
        oh[(size_t)row * 8192 + idx] = 1.f;   // scatter the one
    }
}

// ---------------- quantized output ----------------
__global__ void __launch_bounds__(256) k_quant(const float* __restrict__ cb,
                                               float* __restrict__ out) {
    __shared__ int sidx[32];
    __shared__ float tile[32][257];
    int row0 = blockIdx.x * 32;                 // 32 rows share the same b
    int tid = threadIdx.x, lane = tid & 31, wid = tid >> 5;
    if (tid < 32) sidx[tid] = g_idx[row0 + tid];
    __syncthreads();
    for (int i = wid; i < 32; i += 8) {
        const float* cp = cb + (size_t)sidx[i] * 256;
#pragma unroll
        for (int j = 0; j < 8; j++) tile[i][lane + j * 32] = cp[lane + j * 32];
    }
    __syncthreads();
    int b = row0 >> 10, hw0 = row0 & 1023;
    float* op = out + (size_t)b * 256 * 1024 + hw0;
#pragma unroll
    for (int i = 0; i < 32; i++) {
        int d = i * 8 + wid;
        op[(size_t)d * 1024 + lane] = tile[lane][d];
    }
}

extern "C" void kernel_launch(void* const* d_in, const int* in_sizes, int n_in,
                              void* d_out, int out_size) {
    const float* inputs = (const float*)d_in[0];
    const float* cb     = (const float*)d_in[1];
    if (n_in >= 2 && in_sizes[0] == NC * KD && in_sizes[1] == QUANT_ELEMS) {
        inputs = (const float*)d_in[1];
        cb     = (const float*)d_in[0];
    }
    float* out = (float*)d_out;
    float* oh = out + QUANT_ELEMS;

    cudaFuncSetAttribute(k_gemm, cudaFuncAttributeMaxDynamicSharedMemorySize, GEMM_SMEM);

    k_transpose<<<dim3(32, 8, 16), dim3(32, 8)>>>(inputs);
    k_xsq<<<M_ROWS / 8, 256>>>();
    k_bprep<<<NC * KD / 2 / 256, 256>>>(cb);
    k_gemm<<<128, 512, GEMM_SMEM>>>((char*)oh);
    k_decide<<<M_ROWS / 8, 256>>>(cb, oh);
    k_quant<<<M_ROWS / 32, 256>>>(cb, out);
}

// round 15
// speedup vs baseline: 1.5803x; 1.0030x over previous
#include <cuda_runtime.h>
#include <cuda_bf16.h>
#include <cstdint>

#define M_ROWS 16384
#define KD 256
#define NC 8192
#define QUANT_ELEMS 4194304
#define ONEHOT_ELEMS 134217728
#define THRD 1.25e-4f   // candidate band in dot space (= 2.5e-4 dist / 2)

__device__ float g_A[M_ROWS * KD];           // inputs transposed [row][dim] fp32
__device__ float g_xsq[M_ROWS];
__device__ uint2 g_pairs[M_ROWS * 32];       // per-row 32 (dotbits, col) pairs
__device__ __nv_bfloat16 g_Ab[M_ROWS * KD];  // bf16 copy of A
__device__ __nv_bfloat16 g_Bb[NC * KD];      // bf16 copy of codebook

// ---------------- PTX helpers (sm_80/90 era only; no 'a' features) ----------------
__device__ __forceinline__ uint32_t smem_u32(const void* p) {
    uint32_t a;
    asm("{ .reg .u64 t; cvta.to.shared.u64 t, %1; cvt.u32.u64 %0, t; }" : "=r"(a) : "l"(p));
    return a;
}
#define CP_ASYNC16(dst, src) \
    asm volatile("cp.async.cg.shared.global [%0], [%1], 16;" :: "r"(dst), "l"(src) : "memory")
#define CP_COMMIT() asm volatile("cp.async.commit_group;" ::: "memory")
#define CP_WAIT(n)  asm volatile("cp.async.wait_group %0;" :: "n"(n) : "memory")

// bulk S2G copy (plain cp.async.bulk, sm_90 PTX, not 'a'-gated)
#define BULK_S2G(gdst, ssrc, bytes) \
    asm volatile("cp.async.bulk.global.shared::cta.bulk_group [%0], [%1], %2;" \
                 :: "l"(gdst), "r"(ssrc), "r"(bytes) : "memory")
#define BULK_COMMIT() asm volatile("cp.async.bulk.commit_group;" ::: "memory")
#define BULK_WAIT0()  asm volatile("cp.async.bulk.wait_group 0;" ::: "memory")
#define FENCE_PROXY_ASYNC() asm volatile("fence.proxy.async.shared::cta;" ::: "memory")

__device__ __forceinline__ void ldm_x4(uint32_t* r, uint32_t addr) {
    asm volatile("ldmatrix.sync.aligned.m8n8.x4.shared.b16 {%0,%1,%2,%3}, [%4];"
                 : "=r"(r[0]), "=r"(r[1]), "=r"(r[2]), "=r"(r[3]) : "r"(addr));
}
__device__ __forceinline__ void mma16816(float* d, const uint32_t* a, const uint32_t* b) {
    asm volatile("mma.sync.aligned.m16n8k16.row.col.f32.bf16.bf16.f32 "
                 "{%0,%1,%2,%3}, {%4,%5,%6,%7}, {%8,%9}, {%0,%1,%2,%3};"
                 : "+f"(d[0]), "+f"(d[1]), "+f"(d[2]), "+f"(d[3])
                 : "r"(a[0]), "r"(a[1]), "r"(a[2]), "r"(a[3]), "r"(b[0]), "r"(b[1]));
}
// first-k MMA of a chunk: C = 0 (no acc reset needed)
__device__ __forceinline__ void mma16816_zc(float* d, const uint32_t* a, const uint32_t* b) {
    asm volatile("mma.sync.aligned.m16n8k16.row.col.f32.bf16.bf16.f32 "
                 "{%0,%1,%2,%3}, {%4,%5,%6,%7}, {%8,%9}, {%10,%11,%12,%13};"
                 : "=f"(d[0]), "=f"(d[1]), "=f"(d[2]), "=f"(d[3])
                 : "r"(a[0]), "r"(a[1]), "r"(a[2]), "r"(a[3]), "r"(b[0]), "r"(b[1]),
                   "f"(0.f), "f"(0.f), "f"(0.f), "f"(0.f));
}
__device__ __forceinline__ uint32_t swz(uint32_t byte) {
    return byte ^ ((byte >> 5) & 0x70u);
}

// ---------------- merged prep: transpose (blocks 0..4095) + bprep (rest) ----------------
__global__ void __launch_bounds__(256) k_prep(const float* __restrict__ in,
                                              const float* __restrict__ cb) {
    if (blockIdx.x < 4096) {
        // transpose partition: linear block -> (hw0, c0, b)
        int blk = blockIdx.x;
        int hw0 = (blk & 31) * 32;
        int c0 = ((blk >> 5) & 7) * 32;
        int b = blk >> 8;
        __shared__ float tile[32][33];
        int tx = threadIdx.x & 31, ty = threadIdx.x >> 5;
#pragma unroll
        for (int i = 0; i < 4; i++)
            tile[ty + i * 8][tx] = in[(b * 256 + c0 + ty + i * 8) * 1024 + hw0 + tx];
        __syncthreads();
#pragma unroll
        for (int i = 0; i < 4; i++) {
            float v = tile[tx][ty + i * 8];
            size_t o = (size_t)(b * 1024 + hw0 + ty + i * 8) * 256 + c0 + tx;
            g_A[o] = v;
            g_Ab[o] = __float2bfloat16(v);
        }
    } else {
        // bprep partition: codebook fp32 -> bf16
        int t = (blockIdx.x - 4096) * 256 + threadIdx.x;   // < NC*KD/2
        float2 v = ((const float2*)cb)[t];
        __nv_bfloat162 h;
        h.x = __float2bfloat16(v.x);
        h.y = __float2bfloat16(v.y);
        ((__nv_bfloat162*)g_Bb)[t] = h;
    }
}

__global__ void k_xsq() {
    int warp = threadIdx.x >> 5, lane = threadIdx.x & 31;
    int row = blockIdx.x * 8 + warp;
    const float* p = g_A + (size_t)row * 256;
    float s = 0.f;
#pragma unroll
    for (int i = 0; i < 8; i++) { float v = p[lane + i * 32]; s = __fmaf_rn(v, v, s); }
#pragma unroll
    for (int o = 16; o; o >>= 1) s += __shfl_xor_sync(0xffffffffu, s, o);
    if (lane == 0) g_xsq[row] = s;
}

// ---------------- GEMM + top-2 dots + bulk-engine one-hot zero-fill ----------------
#define SM_A  0u
#define SM_B0 65536u
#define SM_B1 131072u
#define SM_ZERO 196608u
#define GEMM_SMEM (196608 + 16384 + 1024)

__global__ void __launch_bounds__(512, 1) k_gemm(char* __restrict__ ohb) {
    extern __shared__ char smem[];
    uint32_t sbr = smem_u32(smem);
    uint32_t sb = (sbr + 1023u) & ~1023u;
    char* smem_al = smem + (sb - sbr);
    int tid = threadIdx.x;
    int lane = tid & 31, wid = tid >> 5;
    int wm = wid & 3, wn = wid >> 2;           // 4 warps m, 4 warps n
    int m0 = blockIdx.x * 128;

    // zero the bulk-source buffer (16KB)
    {
        float4 z4 = make_float4(0.f, 0.f, 0.f, 0.f);
        float4* z = (float4*)(smem_al + SM_ZERO);
        z[tid] = z4;
        z[tid + 512] = z4;
    }

    // swizzled dst offset decomposes: swz(tid*16 + i*8192) = swz(tid*16) + i*8192
    uint32_t dBase = swz((uint32_t)tid * 16u);

    // prologue: A tile + first two B chunks
    {
        const char* srcA = (const char*)(g_Ab + (size_t)m0 * KD) + tid * 16;
        const char* srcB0 = (const char*)g_Bb + tid * 16;
        const char* srcB1 = (const char*)(g_Bb + 128 * 256) + tid * 16;
#pragma unroll
        for (int i = 0; i < 8; i++)
            CP_ASYNC16(sb + SM_A + dBase + i * 8192, srcA + i * 8192);
#pragma unroll
        for (int i = 0; i < 8; i++)
            CP_ASYNC16(sb + SM_B0 + dBase + i * 8192, srcB0 + i * 8192);
        CP_COMMIT();
#pragma unroll
        for (int i = 0; i < 8; i++)
            CP_ASYNC16(sb + SM_B1 + dBase + i * 8192, srcB1 + i * 8192);
        CP_COMMIT();
    }

    // make the zero buffer visible to the async (bulk) proxy
    __syncthreads();
    if (tid == 0) FENCE_PROXY_ASYNC();
    __syncthreads();

    int rloc0 = wm * 32 + (lane >> 2);         // CTA-local row base

    uint32_t aRow = (uint32_t)(wm * 32 + (lane & 15));
    uint32_t aXor = (aRow & 7u) << 4;
    uint32_t aCfix = (uint32_t)((lane >> 4) * 16);
    uint32_t aBase[2] = { sb + SM_A + aRow * 512, sb + SM_A + (aRow + 16) * 512 };
    uint32_t bRow = (uint32_t)(wn * 32 + ((lane >> 4) * 8) + (lane & 7));
    uint32_t bXor = (bRow & 7u) << 4;
    uint32_t bCfix = (uint32_t)(((lane >> 3) & 1) * 16);
    uint32_t bBase0 = (bRow) * 512;
    uint32_t bBase1 = (bRow + 16) * 512;

    float acc[2][4][4];

    float m1[2][2], m2[2][2];
    int c1[2][2], c2[2][2];
#pragma unroll
    for (int mt = 0; mt < 2; mt++)
#pragma unroll
        for (int h = 0; h < 2; h++) {
            m1[mt][h] = -3.4e38f; m2[mt][h] = -3.4e38f;
            c1[mt][h] = 0; c2[mt][h] = 0;
        }

    for (int s = 0; s < 64; s++) {
        if (s < 63) CP_WAIT(1); else CP_WAIT(0);
        __syncthreads();
        uint32_t bufB = sb + ((s & 1) ? SM_B1 : SM_B0);

        // one-hot zero-fill via bulk engine: 64KB per chunk, zero LSU cost
        if (tid == 0) {
            char* gd = ohb + ((size_t)(blockIdx.x * 64 + s) << 16);
#pragma unroll
            for (int i = 0; i < 4; i++)
                BULK_S2G(gd + i * 16384, sb + SM_ZERO, 16384u);
            BULK_COMMIT();
        }

        // register double-buffered fragment pipeline over ks
        uint32_t fa[2][2][4], fb[2][2][4];
#pragma unroll
        for (int mt = 0; mt < 2; mt++)
            ldm_x4(fa[0][mt], aBase[mt] + ((0 + aCfix) ^ aXor));
        ldm_x4(fb[0][0], bufB + bBase0 + ((0 + bCfix) ^ bXor));
        ldm_x4(fb[0][1], bufB + bBase1 + ((0 + bCfix) ^ bXor));

#pragma unroll
        for (int ks = 0; ks < 16; ks++) {
            int cur = ks & 1, nxt = cur ^ 1;
            if (ks < 15) {
                uint32_t kb = (uint32_t)((ks + 1) * 32);
#pragma unroll
                for (int mt = 0; mt < 2; mt++)
                    ldm_x4(fa[nxt][mt], aBase[mt] + ((kb + aCfix) ^ aXor));
                ldm_x4(fb[nxt][0], bufB + bBase0 + ((kb + bCfix) ^ bXor));
                ldm_x4(fb[nxt][1], bufB + bBase1 + ((kb + bCfix) ^ bXor));
            }
            if (ks == 0) {
#pragma unroll
                for (int mt = 0; mt < 2; mt++)
#pragma unroll
                    for (int nt = 0; nt < 4; nt++)
                        mma16816_zc(acc[mt][nt], fa[cur][mt], &fb[cur][nt >> 1][(nt & 1) * 2]);
            } else {
#pragma unroll
                for (int mt = 0; mt < 2; mt++)
#pragma unroll
                    for (int nt = 0; nt < 4; nt++)
                        mma16816(acc[mt][nt], fa[cur][mt], &fb[cur][nt >> 1][(nt & 1) * 2]);
            }
        }
        __syncthreads();

        if (s + 2 < 64) {
            const char* srcB = (const char*)(g_Bb + (size_t)(s + 2) * 128 * 256) + tid * 16;
#pragma unroll
            for (int i = 0; i < 8; i++)
                CP_ASYNC16(bufB + dBase + i * 8192, srcB + i * 8192);
            CP_COMMIT();
        }

        // ---- epilogue: chunk-max prescreen, rare top-2 update, dots only ----
        int cbase = s * 128 + wn * 32 + (lane & 3) * 2;
#pragma unroll
        for (int mt = 0; mt < 2; mt++)
#pragma unroll
            for (int h = 0; h < 2; h++) {
                float gm = acc[mt][0][h * 2];
                gm = fmaxf(gm, acc[mt][0][h * 2 + 1]);
#pragma unroll
                for (int nt = 1; nt < 4; nt++) {
                    gm = fmaxf(gm, acc[mt][nt][h * 2]);
                    gm = fmaxf(gm, acc[mt][nt][h * 2 + 1]);
                }
                if (gm > m2[mt][h]) {   // rare (~13% of chunks)
#pragma unroll
                    for (int nt = 0; nt < 4; nt++) {
#pragma unroll
                        for (int e = 0; e < 2; e++) {
                            float v = acc[mt][nt][h * 2 + e];
                            int col = cbase + nt * 8 + e;
                            if (v > m1[mt][h]) {
                                m2[mt][h] = m1[mt][h]; c2[mt][h] = c1[mt][h];
                                m1[mt][h] = v;         c1[mt][h] = col;
                            } else if (v > m2[mt][h]) {
                                m2[mt][h] = v;         c2[mt][h] = col;
                            }
                        }
                    }
                }
            }
    }

    // write per-thread top-2 pairs: 32 pairs per row
    int slot = wn * 4 + (lane & 3);
#pragma unroll
    for (int mt = 0; mt < 2; mt++)
#pragma unroll
        for (int h = 0; h < 2; h++) {
            int rg = m0 + rloc0 + mt * 16 + h * 8;
            uint2 p1, p2;
            p1.x = __float_as_uint(m1[mt][h]); p1.y = (unsigned)c1[mt][h];
            p2.x = __float_as_uint(m2[mt][h]); p2.y = (unsigned)c2[mt][h];
            g_pairs[rg * 32 + slot * 2 + 0] = p1;
            g_pairs[rg * 32 + slot * 2 + 1] = p2;
        }

    // drain outstanding bulk zero-fill before kernel end
    if (tid == 0) BULK_WAIT0();
}

// ---------------- decide + one-hot scatter + quant (32 rows / 1024 thr) ----------------
__global__ void __launch_bounds__(1024) k_decide(const float* __restrict__ cb,
                                                 float* __restrict__ oh,
                                                 float* __restrict__ out) {
    __shared__ int sidx[32];
    __shared__ float tile[32][257];
    int tid = threadIdx.x, lane = tid & 31, wid = tid >> 5;
    int row0 = blockIdx.x * 32;
    int row = row0 + wid;

    // --- decide phase: one warp per row ---
    uint2 pr = g_pairs[row * 32 + lane];
    float dot = __uint_as_float(pr.x);
    float wm = dot;
#pragma unroll
    for (int o = 16; o; o >>= 1)
        wm = fmaxf(wm, __shfl_xor_sync(0xffffffffu, wm, o));
    float thr = wm - THRD;

    unsigned long long bk = 0xffffffffffffffffull;
    if (dot >= thr) {
        const float* x = g_A + (size_t)row * 256;
        const float* cp = cb + (size_t)pr.y * 256;
        float sacc = 0.f;
        for (int k = 0; k < 256; k++) sacc = __fmaf_rn(x[k], cp[k], sacc);
        float de = __fmaf_rn(-2.f, sacc, g_xsq[row]);   // == reference fp32 dist
        bk = ((unsigned long long)__float_as_uint(de) << 32) | pr.y;
    }
#pragma unroll
    for (int o = 16; o; o >>= 1) {
        unsigned long long t2 = __shfl_xor_sync(0xffffffffu, bk, o);
        if (t2 < bk) bk = t2;
    }
    int idx = (int)(bk & 0xffffffffu);
    if (lane == 0) {
        sidx[wid] = idx;
        oh[(size_t)row * 8192 + idx] = 1.f;   // scatter the one
    }
    __syncthreads();

    // --- quant phase: warp w stages codebook row for CTA-row w ---
    {
        const float* cp = cb + (size_t)sidx[wid] * 256;
#pragma unroll
        for (int j = 0; j < 8; j++) tile[wid][lane + j * 32] = cp[lane + j * 32];
    }
    __syncthreads();
    int b = row0 >> 10, hw0 = row0 & 1023;
    float* op = out + (size_t)b * 256 * 1024 + hw0;
#pragma unroll
    for (int i = 0; i < 8; i++) {
        int d = i * 32 + wid;
        op[(size_t)d * 1024 + lane] = tile[lane][d];
    }
}

extern "C" void kernel_launch(void* const* d_in, const int* in_sizes, int n_in,
                              void* d_out, int out_size) {
    const float* inputs = (const float*)d_in[0];
    const float* cb     = (const float*)d_in[1];
    if (n_in >= 2 && in_sizes[0] == NC * KD && in_sizes[1] == QUANT_ELEMS) {
        inputs = (const float*)d_in[1];
        cb     = (const float*)d_in[0];
    }
    float* out = (float*)d_out;
    float* oh = out + QUANT_ELEMS;

    cudaFuncSetAttribute(k_gemm, cudaFuncAttributeMaxDynamicSharedMemorySize, GEMM_SMEM);

    k_prep<<<4096 + NC * KD / 2 / 256, 256>>>(inputs, cb);
    k_xsq<<<M_ROWS / 8, 256>>>();
    k_gemm<<<128, 512, GEMM_SMEM>>>((char*)oh);
    k_decide<<<M_ROWS / 32, 1024>>>(cb, oh, out);
}

// round 16
// speedup vs baseline: 1.8073x; 1.1437x over previous
#include <cuda_runtime.h>
#include <cuda_bf16.h>
#include <cstdint>

#define M_ROWS 16384
#define KD 256
#define NC 8192
#define QUANT_ELEMS 4194304
#define ONEHOT_ELEMS 134217728
#define THRD 1.25e-4f   // candidate band in dot space (= 2.5e-4 dist / 2)

__device__ float g_A[M_ROWS * KD];           // inputs transposed [row][dim] fp32
__device__ uint2 g_pairs[M_ROWS * 32];       // per-row 32 (dotbits, col) pairs
__device__ __nv_bfloat16 g_Ab[M_ROWS * KD];  // bf16 copy of A
__device__ __nv_bfloat16 g_Bb[NC * KD];      // bf16 copy of codebook

// ---------------- PTX helpers (sm_80/90 era only; no 'a' features) ----------------
__device__ __forceinline__ uint32_t smem_u32(const void* p) {
    uint32_t a;
    asm("{ .reg .u64 t; cvta.to.shared.u64 t, %1; cvt.u32.u64 %0, t; }" : "=r"(a) : "l"(p));
    return a;
}
#define CP_ASYNC16(dst, src) \
    asm volatile("cp.async.cg.shared.global [%0], [%1], 16;" :: "r"(dst), "l"(src) : "memory")
#define CP_COMMIT() asm volatile("cp.async.commit_group;" ::: "memory")
#define CP_WAIT(n)  asm volatile("cp.async.wait_group %0;" :: "n"(n) : "memory")

// bulk S2G copy (plain cp.async.bulk, sm_90 PTX, not 'a'-gated)
#define BULK_S2G(gdst, ssrc, bytes) \
    asm volatile("cp.async.bulk.global.shared::cta.bulk_group [%0], [%1], %2;" \
                 :: "l"(gdst), "r"(ssrc), "r"(bytes) : "memory")
#define BULK_COMMIT() asm volatile("cp.async.bulk.commit_group;" ::: "memory")
#define BULK_WAIT0()  asm volatile("cp.async.bulk.wait_group 0;" ::: "memory")
#define FENCE_PROXY_ASYNC() asm volatile("fence.proxy.async.shared::cta;" ::: "memory")

__device__ __forceinline__ void ldm_x4(uint32_t* r, uint32_t addr) {
    asm volatile("ldmatrix.sync.aligned.m8n8.x4.shared.b16 {%0,%1,%2,%3}, [%4];"
                 : "=r"(r[0]), "=r"(r[1]), "=r"(r[2]), "=r"(r[3]) : "r"(addr));
}
__device__ __forceinline__ void mma16816(float* d, const uint32_t* a, const uint32_t* b) {
    asm volatile("mma.sync.aligned.m16n8k16.row.col.f32.bf16.bf16.f32 "
                 "{%0,%1,%2,%3}, {%4,%5,%6,%7}, {%8,%9}, {%0,%1,%2,%3};"
                 : "+f"(d[0]), "+f"(d[1]), "+f"(d[2]), "+f"(d[3])
                 : "r"(a[0]), "r"(a[1]), "r"(a[2]), "r"(a[3]), "r"(b[0]), "r"(b[1]));
}
// first-k MMA of a chunk: C = 0 (no acc reset needed)
__device__ __forceinline__ void mma16816_zc(float* d, const uint32_t* a, const uint32_t* b) {
    asm volatile("mma.sync.aligned.m16n8k16.row.col.f32.bf16.bf16.f32 "
                 "{%0,%1,%2,%3}, {%4,%5,%6,%7}, {%8,%9}, {%10,%11,%12,%13};"
                 : "=f"(d[0]), "=f"(d[1]), "=f"(d[2]), "=f"(d[3])
                 : "r"(a[0]), "r"(a[1]), "r"(a[2]), "r"(a[3]), "r"(b[0]), "r"(b[1]),
                   "f"(0.f), "f"(0.f), "f"(0.f), "f"(0.f));
}
__device__ __forceinline__ uint32_t swz(uint32_t byte) {
    return byte ^ ((byte >> 5) & 0x70u);
}

// ---------------- merged prep: transpose (blocks 0..4095) + bprep (rest) ----------------
__global__ void __launch_bounds__(256) k_prep(const float* __restrict__ in,
                                              const float* __restrict__ cb) {
    if (blockIdx.x < 4096) {
        int blk = blockIdx.x;
        int hw0 = (blk & 31) * 32;
        int c0 = ((blk >> 5) & 7) * 32;
        int b = blk >> 8;
        __shared__ float tile[32][33];
        int tx = threadIdx.x & 31, ty = threadIdx.x >> 5;
#pragma unroll
        for (int i = 0; i < 4; i++)
            tile[ty + i * 8][tx] = in[(b * 256 + c0 + ty + i * 8) * 1024 + hw0 + tx];
        __syncthreads();
#pragma unroll
        for (int i = 0; i < 4; i++) {
            float v = tile[tx][ty + i * 8];
            size_t o = (size_t)(b * 1024 + hw0 + ty + i * 8) * 256 + c0 + tx;
            g_A[o] = v;
            g_Ab[o] = __float2bfloat16(v);
        }
    } else {
        int t = (blockIdx.x - 4096) * 256 + threadIdx.x;   // < NC*KD/2
        float2 v = ((const float2*)cb)[t];
        __nv_bfloat162 h;
        h.x = __float2bfloat16(v.x);
        h.y = __float2bfloat16(v.y);
        ((__nv_bfloat162*)g_Bb)[t] = h;
    }
}

// ---------------- GEMM + top-2 dots + bulk-engine one-hot zero-fill ----------------
#define SM_A  0u
#define SM_B0 65536u
#define SM_B1 131072u
#define SM_ZERO 196608u
#define GEMM_SMEM (196608 + 16384 + 1024)

__global__ void __launch_bounds__(512, 1) k_gemm(char* __restrict__ ohb) {
    extern __shared__ char smem[];
    uint32_t sbr = smem_u32(smem);
    uint32_t sb = (sbr + 1023u) & ~1023u;
    char* smem_al = smem + (sb - sbr);
    int tid = threadIdx.x;
    int lane = tid & 31, wid = tid >> 5;
    int wm = wid & 3, wn = wid >> 2;           // 4 warps m, 4 warps n
    int m0 = blockIdx.x * 128;

    // zero the bulk-source buffer (16KB)
    {
        float4 z4 = make_float4(0.f, 0.f, 0.f, 0.f);
        float4* z = (float4*)(smem_al + SM_ZERO);
        z[tid] = z4;
        z[tid + 512] = z4;
    }

    uint32_t dBase = swz((uint32_t)tid * 16u);

    // prologue: A tile + first two B chunks
    {
        const char* srcA = (const char*)(g_Ab + (size_t)m0 * KD) + tid * 16;
        const char* srcB0 = (const char*)g_Bb + tid * 16;
        const char* srcB1 = (const char*)(g_Bb + 128 * 256) + tid * 16;
#pragma unroll
        for (int i = 0; i < 8; i++)
            CP_ASYNC16(sb + SM_A + dBase + i * 8192, srcA + i * 8192);
#pragma unroll
        for (int i = 0; i < 8; i++)
            CP_ASYNC16(sb + SM_B0 + dBase + i * 8192, srcB0 + i * 8192);
        CP_COMMIT();
#pragma unroll
        for (int i = 0; i < 8; i++)
            CP_ASYNC16(sb + SM_B1 + dBase + i * 8192, srcB1 + i * 8192);
        CP_COMMIT();
    }

    __syncthreads();
    if (tid == 0) FENCE_PROXY_ASYNC();
    __syncthreads();

    int rloc0 = wm * 32 + (lane >> 2);         // CTA-local row base

    uint32_t aRow = (uint32_t)(wm * 32 + (lane & 15));
    uint32_t aXor = (aRow & 7u) << 4;
    uint32_t aCfix = (uint32_t)((lane >> 4) * 16);
    uint32_t aBase[2] = { sb + SM_A + aRow * 512, sb + SM_A + (aRow + 16) * 512 };
    uint32_t bRow = (uint32_t)(wn * 32 + ((lane >> 4) * 8) + (lane & 7));
    uint32_t bXor = (bRow & 7u) << 4;
    uint32_t bCfix = (uint32_t)(((lane >> 3) & 1) * 16);
    uint32_t bBase0 = (bRow) * 512;
    uint32_t bBase1 = (bRow + 16) * 512;

    float acc[2][4][4];

    float m1[2][2], m2[2][2];
    int c1[2][2], c2[2][2];
#pragma unroll
    for (int mt = 0; mt < 2; mt++)
#pragma unroll
        for (int h = 0; h < 2; h++) {
            m1[mt][h] = -3.4e38f; m2[mt][h] = -3.4e38f;
            c1[mt][h] = 0; c2[mt][h] = 0;
        }

    for (int s = 0; s < 64; s++) {
        if (s < 63) CP_WAIT(1); else CP_WAIT(0);
        __syncthreads();
        uint32_t bufB = sb + ((s & 1) ? SM_B1 : SM_B0);

        // one-hot zero-fill via bulk engine: 64KB per chunk, zero LSU cost
        if (tid == 0) {
            char* gd = ohb + ((size_t)(blockIdx.x * 64 + s) << 16);
#pragma unroll
            for (int i = 0; i < 4; i++)
                BULK_S2G(gd + i * 16384, sb + SM_ZERO, 16384u);
            BULK_COMMIT();
        }

        // register double-buffered fragment pipeline over ks
        uint32_t fa[2][2][4], fb[2][2][4];
#pragma unroll
        for (int mt = 0; mt < 2; mt++)
            ldm_x4(fa[0][mt], aBase[mt] + ((0 + aCfix) ^ aXor));
        ldm_x4(fb[0][0], bufB + bBase0 + ((0 + bCfix) ^ bXor));
        ldm_x4(fb[0][1], bufB + bBase1 + ((0 + bCfix) ^ bXor));

#pragma unroll
        for (int ks = 0; ks < 16; ks++) {
            int cur = ks & 1, nxt = cur ^ 1;
            if (ks < 15) {
                uint32_t kb = (uint32_t)((ks + 1) * 32);
#pragma unroll
                for (int mt = 0; mt < 2; mt++)
                    ldm_x4(fa[nxt][mt], aBase[mt] + ((kb + aCfix) ^ aXor));
                ldm_x4(fb[nxt][0], bufB + bBase0 + ((kb + bCfix) ^ bXor));
                ldm_x4(fb[nxt][1], bufB + bBase1 + ((kb + bCfix) ^ bXor));
            }
            if (ks == 0) {
#pragma unroll
                for (int mt = 0; mt < 2; mt++)
#pragma unroll
                    for (int nt = 0; nt < 4; nt++)
                        mma16816_zc(acc[mt][nt], fa[cur][mt], &fb[cur][nt >> 1][(nt & 1) * 2]);
            } else {
#pragma unroll
                for (int mt = 0; mt < 2; mt++)
#pragma unroll
                    for (int nt = 0; nt < 4; nt++)
                        mma16816(acc[mt][nt], fa[cur][mt], &fb[cur][nt >> 1][(nt & 1) * 2]);
            }
        }
        __syncthreads();

        if (s + 2 < 64) {
            const char* srcB = (const char*)(g_Bb + (size_t)(s + 2) * 128 * 256) + tid * 16;
#pragma unroll
            for (int i = 0; i < 8; i++)
                CP_ASYNC16(bufB + dBase + i * 8192, srcB + i * 8192);
            CP_COMMIT();
        }

        // ---- epilogue: chunk-max prescreen, rare top-2 update, dots only ----
        int cbase = s * 128 + wn * 32 + (lane & 3) * 2;
#pragma unroll
        for (int mt = 0; mt < 2; mt++)
#pragma unroll
            for (int h = 0; h < 2; h++) {
                float gm = acc[mt][0][h * 2];
                gm = fmaxf(gm, acc[mt][0][h * 2 + 1]);
#pragma unroll
                for (int nt = 1; nt < 4; nt++) {
                    gm = fmaxf(gm, acc[mt][nt][h * 2]);
                    gm = fmaxf(gm, acc[mt][nt][h * 2 + 1]);
                }
                if (gm > m2[mt][h]) {   // rare (~13% of chunks)
#pragma unroll
                    for (int nt = 0; nt < 4; nt++) {
#pragma unroll
                        for (int e = 0; e < 2; e++) {
                            float v = acc[mt][nt][h * 2 + e];
                            int col = cbase + nt * 8 + e;
                            if (v > m1[mt][h]) {
                                m2[mt][h] = m1[mt][h]; c2[mt][h] = c1[mt][h];
                                m1[mt][h] = v;         c1[mt][h] = col;
                            } else if (v > m2[mt][h]) {
                                m2[mt][h] = v;         c2[mt][h] = col;
                            }
                        }
                    }
                }
            }
    }

    // write per-thread top-2 pairs: 32 pairs per row
    int slot = wn * 4 + (lane & 3);
#pragma unroll
    for (int mt = 0; mt < 2; mt++)
#pragma unroll
        for (int h = 0; h < 2; h++) {
            int rg = m0 + rloc0 + mt * 16 + h * 8;
            uint2 p1, p2;
            p1.x = __float_as_uint(m1[mt][h]); p1.y = (unsigned)c1[mt][h];
            p2.x = __float_as_uint(m2[mt][h]); p2.y = (unsigned)c2[mt][h];
            g_pairs[rg * 32 + slot * 2 + 0] = p1;
            g_pairs[rg * 32 + slot * 2 + 1] = p2;
        }

    if (tid == 0) BULK_WAIT0();
}

// ---------------- decide (warp-cooperative) + scatter + quant ----------------
__global__ void __launch_bounds__(1024) k_decide(const float* __restrict__ cb,
                                                 float* __restrict__ oh,
                                                 float* __restrict__ out) {
    __shared__ int sidx[32];
    __shared__ float tile[32][257];
    int tid = threadIdx.x, lane = tid & 31, wid = tid >> 5;
    int row0 = blockIdx.x * 32;
    int row = row0 + wid;

    // x row in registers: lane holds x[lane + 32j] (coalesced)
    const float* x = g_A + (size_t)row * 256;
    float xv[8];
#pragma unroll
    for (int j = 0; j < 8; j++) xv[j] = x[lane + 32 * j];

    // xsq via warp reduction (per-row constant -> any consistent order works)
    float s = 0.f;
#pragma unroll
    for (int j = 0; j < 8; j++) s = __fmaf_rn(xv[j], xv[j], s);
#pragma unroll
    for (int o = 16; o; o >>= 1) s += __shfl_xor_sync(0xffffffffu, s, o);
    float xsq = s;

    // candidate band from recorded pairs
    uint2 pr = g_pairs[row * 32 + lane];
    float dot = __uint_as_float(pr.x);
    float wmx = dot;
#pragma unroll
    for (int o = 16; o; o >>= 1)
        wmx = fmaxf(wmx, __shfl_xor_sync(0xffffffffu, wmx, o));
    unsigned mask = __ballot_sync(0xffffffffu, dot >= wmx - THRD);

    // warp-cooperative exact fp32 dot per candidate (~2-4 per row)
    unsigned long long bk = 0xffffffffffffffffull;
    while (mask) {
        int src = __ffs(mask) - 1;
        mask &= mask - 1;
        int col = __shfl_sync(0xffffffffu, (int)pr.y, src);
        const float* cp = cb + (size_t)col * 256;
        float ps = 0.f;
#pragma unroll
        for (int j = 0; j < 8; j++) ps = __fmaf_rn(xv[j], cp[lane + 32 * j], ps);
#pragma unroll
        for (int o = 16; o; o >>= 1) ps += __shfl_xor_sync(0xffffffffu, ps, o);
        float de = __fmaf_rn(-2.f, ps, xsq);   // fp32 dist, same bin as reference
        unsigned long long key =
            ((unsigned long long)__float_as_uint(de) << 32) | (unsigned)col;
        if (key < bk) bk = key;                // identical on all lanes
    }
    int idx = (int)(bk & 0xffffffffu);
    if (lane == 0) {
        sidx[wid] = idx;
        oh[(size_t)row * 8192 + idx] = 1.f;   // scatter the one
    }
    __syncthreads();

    // --- quant phase: warp w stages codebook row for CTA-row w ---
    {
        const float* cp = cb + (size_t)sidx[wid] * 256;
#pragma unroll
        for (int j = 0; j < 8; j++) tile[wid][lane + j * 32] = cp[lane + j * 32];
    }
    __syncthreads();
    int b = row0 >> 10, hw0 = row0 & 1023;
    float* op = out + (size_t)b * 256 * 1024 + hw0;
#pragma unroll
    for (int i = 0; i < 8; i++) {
        int d = i * 32 + wid;
        op[(size_t)d * 1024 + lane] = tile[lane][d];
    }
}

extern "C" void kernel_launch(void* const* d_in, const int* in_sizes, int n_in,
                              void* d_out, int out_size) {
    const float* inputs = (const float*)d_in[0];
    const float* cb     = (const float*)d_in[1];
    if (n_in >= 2 && in_sizes[0] == NC * KD && in_sizes[1] == QUANT_ELEMS) {
        inputs = (const float*)d_in[1];
        cb     = (const float*)d_in[0];
    }
    float* out = (float*)d_out;
    float* oh = out + QUANT_ELEMS;

    cudaFuncSetAttribute(k_gemm, cudaFuncAttributeMaxDynamicSharedMemorySize, GEMM_SMEM);

    k_prep<<<4096 + NC * KD / 2 / 256, 256>>>(inputs, cb);
    k_gemm<<<128, 512, GEMM_SMEM>>>((char*)oh);
    k_decide<<<M_ROWS / 32, 1024>>>(cb, oh, out);
}